// round 1
// baseline (speedup 1.0000x reference)
#include <cuda_runtime.h>
#include <math.h>

#define Nn 2048
#define D0 256
#define D1 128
#define D2 32
#define Hh 4
#define DHh 64
#define Ff 416      // D0 + D1 + D2
#define NCLS 10
#define NL 4
#define SQRT3 1.7320508075688772f

// ------------------------- device scratch -------------------------
__device__ float g_x0[Nn * D0];
__device__ float g_x1[Nn * D1 * 3];
__device__ float g_x2[Nn * D2 * 5];
__device__ float g_inv[Nn * Ff];
__device__ float g_q[Nn * D0];
__device__ float g_k[Nn * D0];
__device__ float g_attn[(size_t)Hh * Nn * Nn];   // 64 MB
__device__ float g_a[(size_t)Nn * Nn];           // 16 MB
__device__ float g_V[Nn * 704];                  // [v1flat(384) | v2flat(160) | s1(128) | s2(32)]
__device__ float g_v0[Nn * D0];
__device__ float g_agg[Nn * 1088];               // [agg1(384) | agg2(160) | mix1(384) | mix2(160)]
__device__ float g_ff[Nn * 512];
__device__ float g_gate[Nn * 160];

// ------------------------- generic tiled fp32 GEMM -------------------------
// C[M,Ncol](ldc) (+)= act( A[M,K](lda) @ B[K,Ncol](ldb) + bias )
// blockIdx.z batching: A += z*strideA, B += z*strideBC, C += z*strideBC.
// M must be a multiple of 64.
__global__ __launch_bounds__(256)
void gemm_f32(const float* __restrict__ A, const float* __restrict__ B,
              float* __restrict__ C, const float* __restrict__ bias,
              int M, int Ncol, int K, int lda, int ldb, int ldc,
              int act, int accum, size_t strideA, int strideBC)
{
    A += (size_t)blockIdx.z * strideA;
    B += (size_t)blockIdx.z * strideBC;
    C += (size_t)blockIdx.z * strideBC;

    __shared__ float As[16][65];   // [k][row]
    __shared__ float Bs[16][65];   // [k][col]
    int tid = threadIdx.x;
    int tx = tid & 15, ty = tid >> 4;
    int row0 = blockIdx.y * 64, col0 = blockIdx.x * 64;

    float acc[4][4] = {};
    for (int kk = 0; kk < K; kk += 16) {
        for (int i = tid; i < 64 * 16; i += 256) {
            int r = i >> 4, k = i & 15;
            float v = 0.f;
            if (kk + k < K) v = A[(size_t)(row0 + r) * lda + kk + k];
            As[k][r] = v;
        }
        for (int i = tid; i < 16 * 64; i += 256) {
            int k = i >> 6, c = i & 63;
            float v = 0.f;
            if (kk + k < K && col0 + c < Ncol) v = B[(size_t)(kk + k) * ldb + col0 + c];
            Bs[k][c] = v;
        }
        __syncthreads();
#pragma unroll
        for (int k = 0; k < 16; k++) {
            float av[4], bv[4];
#pragma unroll
            for (int i = 0; i < 4; i++) av[i] = As[k][ty * 4 + i];
#pragma unroll
            for (int j = 0; j < 4; j++) bv[j] = Bs[k][tx * 4 + j];
#pragma unroll
            for (int i = 0; i < 4; i++)
#pragma unroll
                for (int j = 0; j < 4; j++)
                    acc[i][j] += av[i] * bv[j];
        }
        __syncthreads();
    }
#pragma unroll
    for (int i = 0; i < 4; i++) {
        int r = row0 + ty * 4 + i;
#pragma unroll
        for (int j = 0; j < 4; j++) {
            int c = col0 + tx * 4 + j;
            if (c < Ncol) {
                float v = acc[i][j];
                if (bias) v += bias[c];
                if (act == 1) v = v / (1.f + __expf(-v));        // silu
                else if (act == 2) v = 1.f / (1.f + __expf(-v)); // sigmoid
                size_t idx = (size_t)r * ldc + c;
                if (accum) C[idx] += v; else C[idx] = v;
            }
        }
    }
}

// ------------------------- attention logits: S[h] = q_h @ k_h^T / 8 -------------------------
__global__ __launch_bounds__(256)
void attn_logits_kernel(const float* __restrict__ q, const float* __restrict__ k)
{
    int h = blockIdx.z;
    int n0 = blockIdx.y * 64, m0 = blockIdx.x * 64;
    __shared__ float Qs[64][65], Ks[64][65];   // [d][row]
    int tid = threadIdx.x;
    for (int i = tid; i < 64 * 64; i += 256) {
        int r = i >> 6, d = i & 63;
        Qs[d][r] = q[(size_t)(n0 + r) * D0 + h * DHh + d];
        Ks[d][r] = k[(size_t)(m0 + r) * D0 + h * DHh + d];
    }
    __syncthreads();
    int tx = tid & 15, ty = tid >> 4;
    float acc[4][4] = {};
#pragma unroll 8
    for (int d = 0; d < 64; d++) {
        float av[4], bv[4];
#pragma unroll
        for (int i = 0; i < 4; i++) av[i] = Qs[d][ty * 4 + i];
#pragma unroll
        for (int j = 0; j < 4; j++) bv[j] = Ks[d][tx * 4 + j];
#pragma unroll
        for (int i = 0; i < 4; i++)
#pragma unroll
            for (int j = 0; j < 4; j++)
                acc[i][j] += av[i] * bv[j];
    }
#pragma unroll
    for (int i = 0; i < 4; i++)
#pragma unroll
        for (int j = 0; j < 4; j++)
            g_attn[((size_t)h * Nn + n0 + ty * 4 + i) * Nn + m0 + tx * 4 + j] = acc[i][j] * 0.125f;
}

// ------------------------- row softmax -------------------------
__global__ __launch_bounds__(256)
void softmax_kernel()
{
    int n = blockIdx.x, h = blockIdx.y;
    float* p = g_attn + ((size_t)h * Nn + n) * Nn;
    __shared__ float red[256];
    int tid = threadIdx.x;

    float mx = -1e30f;
    for (int i = tid; i < Nn; i += 256) mx = fmaxf(mx, p[i]);
    red[tid] = mx; __syncthreads();
    for (int s = 128; s > 0; s >>= 1) { if (tid < s) red[tid] = fmaxf(red[tid], red[tid + s]); __syncthreads(); }
    float m = red[0];
    __syncthreads();

    float sum = 0.f;
    for (int i = tid; i < Nn; i += 256) { float e = __expf(p[i] - m); p[i] = e; sum += e; }
    red[tid] = sum; __syncthreads();
    for (int s = 128; s > 0; s >>= 1) { if (tid < s) red[tid] += red[tid + s]; __syncthreads(); }
    float inv = 1.f / red[0];

    for (int i = tid; i < Nn; i += 256) p[i] *= inv;
}

// ------------------------- mean over heads -------------------------
__global__ void mean_heads_kernel()
{
    const size_t NN = (size_t)Nn * Nn;
    for (size_t i = (size_t)blockIdx.x * blockDim.x + threadIdx.x; i < NN; i += (size_t)gridDim.x * blockDim.x)
        g_a[i] = 0.25f * (g_attn[i] + g_attn[NN + i] + g_attn[2 * NN + i] + g_attn[3 * NN + i]);
}

// ------------------------- invariants -------------------------
__global__ void invariants_kernel()
{
    const int total = Nn * Ff;
    for (int i = blockIdx.x * blockDim.x + threadIdx.x; i < total; i += gridDim.x * blockDim.x) {
        int n = i / Ff, c = i % Ff;
        float v;
        if (c < D0) v = g_x0[n * D0 + c];
        else if (c < D0 + D1) {
            const float* p = &g_x1[(n * D1 + (c - D0)) * 3];
            v = sqrtf(p[0] * p[0] + p[1] * p[1] + p[2] * p[2]);
        } else {
            const float* p = &g_x2[(n * D2 + (c - D0 - D1)) * 5];
            v = sqrtf(p[0] * p[0] + p[1] * p[1] + p[2] * p[2] + p[3] * p[3] + p[4] * p[4]);
        }
        g_inv[i] = v;
    }
}

// ------------------------- v1 = einsum('mdc,de->mec') -------------------------
__global__ __launch_bounds__(128)
void v1_kernel(const float* __restrict__ Wv1)
{
    int m = blockIdx.x;
    __shared__ float sx[D1 * 3];
    int tid = threadIdx.x; // 128
    for (int i = tid; i < D1 * 3; i += 128) sx[i] = g_x1[m * D1 * 3 + i];
    __syncthreads();
    float a0 = 0.f, a1 = 0.f, a2 = 0.f;
#pragma unroll 8
    for (int d = 0; d < D1; d++) {
        float w = Wv1[d * D1 + tid];
        a0 += sx[d * 3 + 0] * w;
        a1 += sx[d * 3 + 1] * w;
        a2 += sx[d * 3 + 2] * w;
    }
    float* o = &g_V[m * 704 + tid * 3];
    o[0] = a0; o[1] = a1; o[2] = a2;
}

__global__ __launch_bounds__(32)
void v2_kernel(const float* __restrict__ Wv2)
{
    int m = blockIdx.x;
    __shared__ float sx[D2 * 5];
    int tid = threadIdx.x; // 32
    for (int i = tid; i < D2 * 5; i += 32) sx[i] = g_x2[m * D2 * 5 + i];
    __syncthreads();
    float a[5] = {};
#pragma unroll 8
    for (int d = 0; d < D2; d++) {
        float w = Wv2[d * D2 + tid];
#pragma unroll
        for (int c = 0; c < 5; c++) a[c] += sx[d * 5 + c] * w;
    }
#pragma unroll
    for (int c = 0; c < 5; c++) g_V[m * 704 + 384 + tid * 5 + c] = a[c];
}

// ------------------------- fused agg/mix GEMM -------------------------
// out[n, col] = sum_m w_{cls(col)}(n,m) * V[m, vcol(col)]
// cols: [0,544)   -> class 0 (w=a),           vcol=col          (agg1,agg2)
//       [544,928) -> class 1+c (w=a*Y1c),     vcol=544+d        (mix1, col=544+c*128+d)
//       [928,1088)-> class 4+c (w=a*Y2c),     vcol=672+e        (mix2, col=928+c*32+e)
__device__ __forceinline__ int colcls(int col) {
    return col < 544 ? 0 : (col < 928 ? 1 + ((col - 544) >> 7) : 4 + ((col - 928) >> 5));
}
__device__ __forceinline__ int colv(int col) {
    return col < 544 ? col : (col < 928 ? 544 + ((col - 544) & 127) : 672 + ((col - 928) & 31));
}
__device__ __forceinline__ float yfac(int cls, float ux, float uy, float uz, float valid) {
    switch (cls) {
        case 0: return 1.f;
        case 1: return ux;
        case 2: return uy;
        case 3: return uz;
        case 4: return SQRT3 * ux * uy * valid;
        case 5: return SQRT3 * uy * uz * valid;
        case 6: return 0.5f * (3.f * uz * uz - 1.f) * valid;
        case 7: return SQRT3 * ux * uz * valid;
        default: return 0.5f * SQRT3 * (ux * ux - uy * uy) * valid;
    }
}

__global__ __launch_bounds__(256, 2)
void aggmix_kernel(const float* __restrict__ pos)
{
    // block tile: 128 rows (n) x 64 cols, K-chunk 32. thread tile 8x4.
    __shared__ float As[2][32][132];
    __shared__ float Bs[32][68];
    __shared__ float posN[128][3];
    __shared__ float posM[32][3];

    int tid = threadIdx.x;
    int n0 = blockIdx.y * 128;
    int col0 = blockIdx.x * 64;
    int clsA = colcls(col0);
    int clsB = colcls(col0 + 63);
    bool two = (clsB != clsA);

    for (int i = tid; i < 128 * 3; i += 256)
        posN[i / 3][i % 3] = pos[(n0 + i / 3) * 3 + i % 3];

    int tx = tid & 15, ty = tid >> 4;
    int ci[4];
#pragma unroll
    for (int j = 0; j < 4; j++)
        ci[j] = (colcls(col0 + tx * 4 + j) == clsA) ? 0 : 1;

    float acc[8][4] = {};

    for (int m0 = 0; m0 < Nn; m0 += 32) {
        __syncthreads();   // prev compute done before smem overwrite
        if (tid < 96) posM[tid / 3][tid % 3] = pos[(m0 + tid / 3) * 3 + tid % 3];
        for (int i = tid; i < 32 * 64; i += 256) {
            int k = i >> 6, j = i & 63;
            Bs[k][j] = g_V[(size_t)(m0 + k) * 704 + colv(col0 + j)];
        }
        __syncthreads();   // posM ready
        for (int i = tid; i < 128 * 32; i += 256) {
            int r = i >> 5, k = i & 31;
            float av = g_a[(size_t)(n0 + r) * Nn + m0 + k];
            float rx = posM[k][0] - posN[r][0];
            float ry = posM[k][1] - posN[r][1];
            float rz = posM[k][2] - posN[r][2];
            float dist = sqrtf(rx * rx + ry * ry + rz * rz);
            float valid = dist > 1e-6f ? 1.f : 0.f;
            float inv = valid / fmaxf(dist, 1e-6f);
            float ux = rx * inv, uy = ry * inv, uz = rz * inv;
            As[0][k][r] = av * yfac(clsA, ux, uy, uz, valid);
            if (two) As[1][k][r] = av * yfac(clsB, ux, uy, uz, valid);
        }
        __syncthreads();
#pragma unroll 8
        for (int k = 0; k < 32; k++) {
            float bv[4];
#pragma unroll
            for (int j = 0; j < 4; j++) bv[j] = Bs[k][tx * 4 + j];
            float a0[8], a1[8];
#pragma unroll
            for (int i = 0; i < 8; i++) a0[i] = As[0][k][ty * 8 + i];
            if (two) {
#pragma unroll
                for (int i = 0; i < 8; i++) a1[i] = As[1][k][ty * 8 + i];
#pragma unroll
                for (int i = 0; i < 8; i++)
#pragma unroll
                    for (int j = 0; j < 4; j++)
                        acc[i][j] += (ci[j] ? a1[i] : a0[i]) * bv[j];
            } else {
#pragma unroll
                for (int i = 0; i < 8; i++)
#pragma unroll
                    for (int j = 0; j < 4; j++)
                        acc[i][j] += a0[i] * bv[j];
            }
        }
    }
#pragma unroll
    for (int i = 0; i < 8; i++) {
        size_t r = (size_t)(n0 + ty * 8 + i);
#pragma unroll
        for (int j = 0; j < 4; j++)
            g_agg[r * 1088 + col0 + tx * 4 + j] = acc[i][j];
    }
}

// ------------------------- finalize: x1 += agg1+mix1 ; x2 += agg2+mix2 -------------------------
__global__ void finalize_kernel()
{
    const int total = Nn * 544;
    for (int i = blockIdx.x * blockDim.x + threadIdx.x; i < total; i += gridDim.x * blockDim.x) {
        int n = i / 544, t = i % 544;
        if (t < 384) {
            int d = t / 3, c = t % 3;
            g_x1[n * 384 + t] += g_agg[(size_t)n * 1088 + t] + g_agg[(size_t)n * 1088 + 544 + c * 128 + d];
        } else {
            int tt = t - 384, e = tt / 5, c = tt % 5;
            g_x2[n * 160 + tt] += g_agg[(size_t)n * 1088 + 384 + tt] + g_agg[(size_t)n * 1088 + 928 + c * 32 + e];
        }
    }
}

// ------------------------- apply gate -------------------------
__global__ void gate_kernel()
{
    const int total = Nn * 544;
    for (int i = blockIdx.x * blockDim.x + threadIdx.x; i < total; i += gridDim.x * blockDim.x) {
        int n = i / 544, t = i % 544;
        if (t < 384) g_x1[n * 384 + t] *= g_gate[n * 160 + t / 3];
        else { int tt = t - 384; g_x2[n * 160 + tt] *= g_gate[n * 160 + 128 + tt / 5]; }
    }
}

// ------------------------- zero x1/x2 -------------------------
__global__ void zero_kernel()
{
    const int t1 = Nn * 384, total = Nn * 384 + Nn * 160;
    for (int i = blockIdx.x * blockDim.x + threadIdx.x; i < total; i += gridDim.x * blockDim.x) {
        if (i < t1) g_x1[i] = 0.f; else g_x2[i - t1] = 0.f;
    }
}

// ------------------------- host launcher -------------------------
extern "C" void kernel_launch(void* const* d_in, const int* in_sizes, int n_in,
                              void* d_out, int out_size)
{
    const float* x     = (const float*)d_in[0];
    const float* pos   = (const float*)d_in[1];
    const float* emb_W = (const float*)d_in[2];
    const float* emb_b = (const float*)d_in[3];
    const float* Wq    = (const float*)d_in[4];
    const float* Wk    = (const float*)d_in[5];
    const float* Wv0   = (const float*)d_in[6];
    const float* Wv1   = (const float*)d_in[7];
    const float* Wv2   = (const float*)d_in[8];
    const float* Ws1   = (const float*)d_in[9];
    const float* Ws2   = (const float*)d_in[10];
    const float* Wffa  = (const float*)d_in[11];
    const float* Wffb  = (const float*)d_in[12];
    const float* Wg    = (const float*)d_in[13];
    const float* out_W = (const float*)d_in[14];
    const float* out_b = (const float*)d_in[15];
    float* out = (float*)d_out;

    void* vp;
    cudaGetSymbolAddress(&vp, g_x0);   float* px0   = (float*)vp;
    cudaGetSymbolAddress(&vp, g_inv);  float* pinv  = (float*)vp;
    cudaGetSymbolAddress(&vp, g_q);    float* pq    = (float*)vp;
    cudaGetSymbolAddress(&vp, g_k);    float* pk    = (float*)vp;
    cudaGetSymbolAddress(&vp, g_attn); float* pattn = (float*)vp;
    cudaGetSymbolAddress(&vp, g_V);    float* pV    = (float*)vp;
    cudaGetSymbolAddress(&vp, g_v0);   float* pv0   = (float*)vp;
    cudaGetSymbolAddress(&vp, g_ff);   float* pff   = (float*)vp;
    cudaGetSymbolAddress(&vp, g_gate); float* pgate = (float*)vp;

    zero_kernel<<<512, 256>>>();
    // x0 = x @ emb_W + emb_b
    gemm_f32<<<dim3(4, 32), 256>>>(x, emb_W, px0, emb_b, Nn, D0, 118, 118, D0, D0, 0, 0, 0, 0);

    for (int l = 0; l < NL; l++) {
        const float* Wq_l   = Wq   + (size_t)l * Ff * D0;
        const float* Wk_l   = Wk   + (size_t)l * Ff * D0;
        const float* Wv0_l  = Wv0  + (size_t)l * D0 * D0;
        const float* Wv1_l  = Wv1  + (size_t)l * D1 * D1;
        const float* Wv2_l  = Wv2  + (size_t)l * D2 * D2;
        const float* Ws1_l  = Ws1  + (size_t)l * D0 * D1;
        const float* Ws2_l  = Ws2  + (size_t)l * D0 * D2;
        const float* Wffa_l = Wffa + (size_t)l * D0 * 512;
        const float* Wffb_l = Wffb + (size_t)l * 512 * D0;
        const float* Wg_l   = Wg   + (size_t)l * Ff * 160;

        invariants_kernel<<<1024, 256>>>();
        gemm_f32<<<dim3(4, 32), 256>>>(pinv, Wq_l, pq, nullptr, Nn, D0, Ff, Ff, D0, D0, 0, 0, 0, 0);
        gemm_f32<<<dim3(4, 32), 256>>>(pinv, Wk_l, pk, nullptr, Nn, D0, Ff, Ff, D0, D0, 0, 0, 0, 0);
        gemm_f32<<<dim3(4, 32), 256>>>(px0, Wv0_l, pv0, nullptr, Nn, D0, D0, D0, D0, D0, 0, 0, 0, 0);
        gemm_f32<<<dim3(2, 32), 256>>>(px0, Ws1_l, pV + 544, nullptr, Nn, D1, D0, D0, D1, 704, 0, 0, 0, 0);
        gemm_f32<<<dim3(1, 32), 256>>>(px0, Ws2_l, pV + 672, nullptr, Nn, D2, D0, D0, D2, 704, 0, 0, 0, 0);
        v1_kernel<<<Nn, 128>>>(Wv1_l);
        v2_kernel<<<Nn, 32>>>(Wv2_l);

        attn_logits_kernel<<<dim3(32, 32, 4), 256>>>(pq, pk);
        softmax_kernel<<<dim3(Nn, Hh), 256>>>();
        mean_heads_kernel<<<2048, 256>>>();

        // x0 += attn_h @ v0_h (batched over heads)
        gemm_f32<<<dim3(1, 32, 4), 256>>>(pattn, pv0, px0, nullptr,
                                          Nn, DHh, Nn, Nn, D0, D0, 0, 1,
                                          (size_t)Nn * Nn, DHh);

        aggmix_kernel<<<dim3(17, 16), 256>>>(pos);
        finalize_kernel<<<1024, 256>>>();

        // feedforward: x0 += silu(x0 @ Wffa) @ Wffb
        gemm_f32<<<dim3(8, 32), 256>>>(px0, Wffa_l, pff, nullptr, Nn, 512, D0, D0, 512, 512, 1, 0, 0, 0);
        gemm_f32<<<dim3(4, 32), 256>>>(pff, Wffb_l, px0, nullptr, Nn, D0, 512, 512, D0, D0, 0, 1, 0, 0);

        // gate
        invariants_kernel<<<1024, 256>>>();
        gemm_f32<<<dim3(3, 32), 256>>>(pinv, Wg_l, pgate, nullptr, Nn, 160, Ff, Ff, 160, 160, 2, 0, 0, 0);
        gate_kernel<<<1024, 256>>>();
    }

    // out = x0 @ out_W + out_b
    gemm_f32<<<dim3(1, 32), 256>>>(px0, out_W, out, out_b, Nn, NCLS, D0, D0, NCLS, NCLS, 0, 0, 0, 0);
}

// round 2
// speedup vs baseline: 1.6259x; 1.6259x over previous
#include <cuda_runtime.h>
#include <math.h>

#define Nn 2048
#define D0 256
#define D1 128
#define D2 32
#define Hh 4
#define DHh 64
#define Ff 416      // D0 + D1 + D2
#define NCLS 10
#define NL 4
#define SQRT3 1.7320508075688772f
#define NNsz ((size_t)Nn * Nn)

// ------------------------- device scratch -------------------------
__device__ float g_x0[Nn * D0];
__device__ float g_x1[Nn * D1 * 3];
__device__ float g_x2[Nn * D2 * 5];
__device__ float g_inv[Nn * Ff];
__device__ float g_q[Nn * D0];
__device__ float g_k[Nn * D0];
__device__ float g_attn[(size_t)Hh * Nn * Nn];   // 64 MB
__device__ float g_a[NNsz];                      // 16 MB (class-0 weight)
__device__ float g_W[8 * NNsz];                  // 128 MB (classes 1..8: a*Y)
__device__ float g_V[Nn * 704];                  // [v1flat(384) | v2flat(160) | s1(128) | s2(32)]
__device__ float g_v0[Nn * D0];
__device__ float g_agg[Nn * 1088];               // [agg1(384) | agg2(160) | mix1(384) | mix2(160)]
__device__ float g_ff[Nn * 512];
__device__ float g_gate[Nn * 160];
__device__ float g_part[4 * Nn * D0];            // split-K partials for attn@v0

// ------------------------- generic tiled fp32 GEMM v2 -------------------------
// 64x64 block tile, 256 threads, 4x4 micro-tile, float4 LDS, double-buffered smem.
// C[M,Ncol](ldc) (+)= act( A[M,K](lda) @ B[K,Ncol](ldb) + bias )
// z decomposition: z1 = z % zdiv, z2 = z / zdiv; ptr += z1*s?1 + z2*s?2.
__device__ __forceinline__ void gemm_load(
    const float* __restrict__ A, const float* __restrict__ B,
    float (*As)[68], float (*Bs)[68],
    int row0, int col0, int kk, int Ncol, int K, int lda, int ldb,
    int tid, bool vecA, bool vecB)
{
    if (vecA) {
        int r = tid >> 2, k4 = (tid & 3) * 4;
        float4 v = *(const float4*)&A[(size_t)(row0 + r) * lda + kk + k4];
        As[k4 + 0][r] = v.x; As[k4 + 1][r] = v.y; As[k4 + 2][r] = v.z; As[k4 + 3][r] = v.w;
    } else {
        for (int i = tid; i < 64 * 16; i += 256) {
            int r = i >> 4, k = i & 15;
            As[k][r] = (kk + k < K) ? A[(size_t)(row0 + r) * lda + kk + k] : 0.f;
        }
    }
    if (vecB) {
        int k = tid >> 4, c4 = (tid & 15) * 4;
        float4 v = make_float4(0.f, 0.f, 0.f, 0.f);
        if (kk + k < K) {
            if (col0 + c4 + 3 < Ncol) {
                v = *(const float4*)&B[(size_t)(kk + k) * ldb + col0 + c4];
            } else {
                const float* bp = &B[(size_t)(kk + k) * ldb];
                if (col0 + c4 + 0 < Ncol) v.x = bp[col0 + c4 + 0];
                if (col0 + c4 + 1 < Ncol) v.y = bp[col0 + c4 + 1];
                if (col0 + c4 + 2 < Ncol) v.z = bp[col0 + c4 + 2];
                if (col0 + c4 + 3 < Ncol) v.w = bp[col0 + c4 + 3];
            }
        }
        *(float4*)&Bs[k][c4] = v;
    } else {
        for (int i = tid; i < 16 * 64; i += 256) {
            int k = i >> 6, c = i & 63;
            float v = 0.f;
            if (kk + k < K && col0 + c < Ncol) v = B[(size_t)(kk + k) * ldb + col0 + c];
            Bs[k][c] = v;
        }
    }
}

__global__ __launch_bounds__(256)
void gemm_f32(const float* __restrict__ A, const float* __restrict__ B,
              float* __restrict__ C, const float* __restrict__ bias,
              int M, int Ncol, int K, int lda, int ldb, int ldc,
              int act, int accum, int zdiv,
              size_t sA1, size_t sA2, size_t sB1, size_t sB2, size_t sC1, size_t sC2)
{
    int z1 = blockIdx.z % zdiv, z2 = blockIdx.z / zdiv;
    A += (size_t)z1 * sA1 + (size_t)z2 * sA2;
    B += (size_t)z1 * sB1 + (size_t)z2 * sB2;
    C += (size_t)z1 * sC1 + (size_t)z2 * sC2;

    __shared__ float As[2][16][68];
    __shared__ float Bs[2][16][68];
    int tid = threadIdx.x;
    int tx = tid & 15, ty = tid >> 4;
    int row0 = blockIdx.y * 64, col0 = blockIdx.x * 64;
    bool vecA = ((lda & 3) == 0) && ((K & 15) == 0);
    bool vecB = ((ldb & 3) == 0);

    float acc[4][4] = {};
    int nChunks = (K + 15) >> 4;
    int buf = 0;
    gemm_load(A, B, As[0], Bs[0], row0, col0, 0, Ncol, K, lda, ldb, tid, vecA, vecB);
    __syncthreads();
    for (int c = 1; c < nChunks; c++) {
        gemm_load(A, B, As[buf ^ 1], Bs[buf ^ 1], row0, col0, c * 16, Ncol, K, lda, ldb, tid, vecA, vecB);
#pragma unroll
        for (int k = 0; k < 16; k++) {
            float4 av = *(float4*)&As[buf][k][ty * 4];
            float4 bv = *(float4*)&Bs[buf][k][tx * 4];
            float a[4] = {av.x, av.y, av.z, av.w};
            float b[4] = {bv.x, bv.y, bv.z, bv.w};
#pragma unroll
            for (int i = 0; i < 4; i++)
#pragma unroll
                for (int j = 0; j < 4; j++) acc[i][j] += a[i] * b[j];
        }
        __syncthreads();
        buf ^= 1;
    }
#pragma unroll
    for (int k = 0; k < 16; k++) {
        float4 av = *(float4*)&As[buf][k][ty * 4];
        float4 bv = *(float4*)&Bs[buf][k][tx * 4];
        float a[4] = {av.x, av.y, av.z, av.w};
        float b[4] = {bv.x, bv.y, bv.z, bv.w};
#pragma unroll
        for (int i = 0; i < 4; i++)
#pragma unroll
            for (int j = 0; j < 4; j++) acc[i][j] += a[i] * b[j];
    }

#pragma unroll
    for (int i = 0; i < 4; i++) {
        int r = row0 + ty * 4 + i;
#pragma unroll
        for (int j = 0; j < 4; j++) {
            int c = col0 + tx * 4 + j;
            if (c < Ncol) {
                float v = acc[i][j];
                if (bias) v += bias[c];
                if (act == 1) v = v / (1.f + __expf(-v));        // silu
                else if (act == 2) v = 1.f / (1.f + __expf(-v)); // sigmoid
                size_t idx = (size_t)r * ldc + c;
                if (accum) C[idx] += v; else C[idx] = v;
            }
        }
    }
}

// ------------------------- attention logits: S[h] = q_h @ k_h^T / 8 -------------------------
__global__ __launch_bounds__(256)
void attn_logits_kernel(const float* __restrict__ q, const float* __restrict__ k)
{
    int h = blockIdx.z;
    int n0 = blockIdx.y * 64, m0 = blockIdx.x * 64;
    __shared__ float Qs[64][68], Ks[64][68];   // [d][row]
    int tid = threadIdx.x;
    for (int i = tid; i < 64 * 64; i += 256) {
        int r = i >> 6, d = i & 63;
        Qs[d][r] = q[(size_t)(n0 + r) * D0 + h * DHh + d];
        Ks[d][r] = k[(size_t)(m0 + r) * D0 + h * DHh + d];
    }
    __syncthreads();
    int tx = tid & 15, ty = tid >> 4;
    float acc[4][4] = {};
#pragma unroll 8
    for (int d = 0; d < 64; d++) {
        float4 av = *(float4*)&Qs[d][ty * 4];
        float4 bv = *(float4*)&Ks[d][tx * 4];
        float a[4] = {av.x, av.y, av.z, av.w};
        float b[4] = {bv.x, bv.y, bv.z, bv.w};
#pragma unroll
        for (int i = 0; i < 4; i++)
#pragma unroll
            for (int j = 0; j < 4; j++) acc[i][j] += a[i] * b[j];
    }
#pragma unroll
    for (int i = 0; i < 4; i++)
#pragma unroll
        for (int j = 0; j < 4; j++)
            g_attn[((size_t)h * Nn + n0 + ty * 4 + i) * Nn + m0 + tx * 4 + j] = acc[i][j] * 0.125f;
}

// ------------------------- row softmax (smem row buffer: 1 read + 1 write) -------------------------
__global__ __launch_bounds__(256)
void softmax_kernel()
{
    int n = blockIdx.x, h = blockIdx.y;
    float* p = g_attn + ((size_t)h * Nn + n) * Nn;
    __shared__ float row[Nn];
    __shared__ float red[256];
    int tid = threadIdx.x;

    float mx = -1e30f;
    for (int i = tid * 4; i < Nn; i += 1024) {
        float4 v = *(const float4*)&p[i];
        *(float4*)&row[i] = v;
        mx = fmaxf(mx, fmaxf(fmaxf(v.x, v.y), fmaxf(v.z, v.w)));
    }
    red[tid] = mx; __syncthreads();
    for (int s = 128; s > 0; s >>= 1) { if (tid < s) red[tid] = fmaxf(red[tid], red[tid + s]); __syncthreads(); }
    float m = red[0];
    __syncthreads();

    float sum = 0.f;
    for (int i = tid; i < Nn; i += 256) { float e = __expf(row[i] - m); row[i] = e; sum += e; }
    red[tid] = sum; __syncthreads();
    for (int s = 128; s > 0; s >>= 1) { if (tid < s) red[tid] += red[tid + s]; __syncthreads(); }
    float inv = 1.f / red[0];
    __syncthreads();

    for (int i = tid * 4; i < Nn; i += 1024) {
        float4 v = *(float4*)&row[i];
        v.x *= inv; v.y *= inv; v.z *= inv; v.w *= inv;
        *(float4*)&p[i] = v;
    }
}

// ------------------------- build per-layer class weight matrices -------------------------
// a = mean over heads; W[c-1] = a * Y_c  (classes 1..8). Class 0 weight IS a.
__global__ void build_w_kernel(const float* __restrict__ pos)
{
    for (size_t idx = (size_t)blockIdx.x * blockDim.x + threadIdx.x; idx < NNsz;
         idx += (size_t)gridDim.x * blockDim.x) {
        int n = (int)(idx >> 11), m = (int)(idx & 2047);
        float a = 0.25f * (g_attn[idx] + g_attn[NNsz + idx] + g_attn[2 * NNsz + idx] + g_attn[3 * NNsz + idx]);
        g_a[idx] = a;
        float rx = pos[m * 3 + 0] - pos[n * 3 + 0];
        float ry = pos[m * 3 + 1] - pos[n * 3 + 1];
        float rz = pos[m * 3 + 2] - pos[n * 3 + 2];
        float r2 = rx * rx + ry * ry + rz * rz;
        bool ok = r2 > 1e-12f;
        float inv = ok ? rsqrtf(r2) : 0.f;
        float valid = ok ? 1.f : 0.f;
        float ux = rx * inv, uy = ry * inv, uz = rz * inv;
        g_W[0 * NNsz + idx] = a * ux;
        g_W[1 * NNsz + idx] = a * uy;
        g_W[2 * NNsz + idx] = a * uz;
        g_W[3 * NNsz + idx] = a * (SQRT3 * ux * uy);
        g_W[4 * NNsz + idx] = a * (SQRT3 * uy * uz);
        g_W[5 * NNsz + idx] = a * (0.5f * (3.f * uz * uz - 1.f)) * valid;
        g_W[6 * NNsz + idx] = a * (SQRT3 * ux * uz);
        g_W[7 * NNsz + idx] = a * (0.5f * SQRT3 * (ux * ux - uy * uy));
    }
}

// ------------------------- invariants -------------------------
__global__ void invariants_kernel()
{
    const int total = Nn * Ff;
    for (int i = blockIdx.x * blockDim.x + threadIdx.x; i < total; i += gridDim.x * blockDim.x) {
        int n = i / Ff, c = i % Ff;
        float v;
        if (c < D0) v = g_x0[n * D0 + c];
        else if (c < D0 + D1) {
            const float* p = &g_x1[(n * D1 + (c - D0)) * 3];
            v = sqrtf(p[0] * p[0] + p[1] * p[1] + p[2] * p[2]);
        } else {
            const float* p = &g_x2[(n * D2 + (c - D0 - D1)) * 5];
            v = sqrtf(p[0] * p[0] + p[1] * p[1] + p[2] * p[2] + p[3] * p[3] + p[4] * p[4]);
        }
        g_inv[i] = v;
    }
}

// ------------------------- v1/v2 channel mixes -------------------------
__global__ __launch_bounds__(128)
void v1_kernel(const float* __restrict__ Wv1)
{
    int m = blockIdx.x;
    __shared__ float sx[D1 * 3];
    int tid = threadIdx.x;
    for (int i = tid; i < D1 * 3; i += 128) sx[i] = g_x1[m * D1 * 3 + i];
    __syncthreads();
    float a0 = 0.f, a1 = 0.f, a2 = 0.f;
#pragma unroll 8
    for (int d = 0; d < D1; d++) {
        float w = Wv1[d * D1 + tid];
        a0 += sx[d * 3 + 0] * w;
        a1 += sx[d * 3 + 1] * w;
        a2 += sx[d * 3 + 2] * w;
    }
    float* o = &g_V[m * 704 + tid * 3];
    o[0] = a0; o[1] = a1; o[2] = a2;
}

__global__ __launch_bounds__(32)
void v2_kernel(const float* __restrict__ Wv2)
{
    int m = blockIdx.x;
    __shared__ float sx[D2 * 5];
    int tid = threadIdx.x;
    for (int i = tid; i < D2 * 5; i += 32) sx[i] = g_x2[m * D2 * 5 + i];
    __syncthreads();
    float a[5] = {};
#pragma unroll 8
    for (int d = 0; d < D2; d++) {
        float w = Wv2[d * D2 + tid];
#pragma unroll
        for (int c = 0; c < 5; c++) a[c] += sx[d * 5 + c] * w;
    }
#pragma unroll
    for (int c = 0; c < 5; c++) g_V[m * 704 + 384 + tid * 5 + c] = a[c];
}

// ------------------------- fused agg/mix GEMM (reads prebuilt W) -------------------------
__device__ __forceinline__ int colcls(int col) {
    return col < 544 ? 0 : (col < 928 ? 1 + ((col - 544) >> 7) : 4 + ((col - 928) >> 5));
}
__device__ __forceinline__ int colv(int col) {
    return col < 544 ? col : (col < 928 ? 544 + ((col - 544) & 127) : 672 + ((col - 928) & 31));
}

__global__ __launch_bounds__(256, 2)
void aggmix_kernel()
{
    __shared__ float As[2][32][132];
    __shared__ float Bs[32][68];

    int tid = threadIdx.x;
    int n0 = blockIdx.y * 128;
    int col0 = blockIdx.x * 64;
    int clsA = colcls(col0);
    int clsB = colcls(col0 + 63);
    bool two = (clsB != clsA);
    const float* WA = (clsA == 0) ? g_a : g_W + (size_t)(clsA - 1) * NNsz;
    const float* WB = (clsB == 0) ? g_a : g_W + (size_t)(clsB - 1) * NNsz;

    int tx = tid & 15, ty = tid >> 4;
    int ci[4];
#pragma unroll
    for (int j = 0; j < 4; j++)
        ci[j] = (colcls(col0 + tx * 4 + j) != clsA);

    float acc[8][4] = {};

    for (int m0 = 0; m0 < Nn; m0 += 32) {
        __syncthreads();
        for (int i = tid; i < 32 * 64; i += 256) {
            int k = i >> 6, j = i & 63;
            Bs[k][j] = g_V[(size_t)(m0 + k) * 704 + colv(col0 + j)];
        }
        for (int i = tid; i < 128 * 32; i += 256) {
            int r = i >> 5, k = i & 31;
            As[0][k][r] = WA[(size_t)(n0 + r) * Nn + m0 + k];
        }
        if (two) {
            for (int i = tid; i < 128 * 32; i += 256) {
                int r = i >> 5, k = i & 31;
                As[1][k][r] = WB[(size_t)(n0 + r) * Nn + m0 + k];
            }
        }
        __syncthreads();
        if (two) {
#pragma unroll 4
            for (int k = 0; k < 32; k++) {
                float4 bv = *(float4*)&Bs[k][tx * 4];
                float b[4] = {bv.x, bv.y, bv.z, bv.w};
                float4 a0l = *(float4*)&As[0][k][ty * 8];
                float4 a0h = *(float4*)&As[0][k][ty * 8 + 4];
                float4 a1l = *(float4*)&As[1][k][ty * 8];
                float4 a1h = *(float4*)&As[1][k][ty * 8 + 4];
                float a0[8] = {a0l.x, a0l.y, a0l.z, a0l.w, a0h.x, a0h.y, a0h.z, a0h.w};
                float a1[8] = {a1l.x, a1l.y, a1l.z, a1l.w, a1h.x, a1h.y, a1h.z, a1h.w};
#pragma unroll
                for (int i = 0; i < 8; i++)
#pragma unroll
                    for (int j = 0; j < 4; j++)
                        acc[i][j] += (ci[j] ? a1[i] : a0[i]) * b[j];
            }
        } else {
#pragma unroll 4
            for (int k = 0; k < 32; k++) {
                float4 bv = *(float4*)&Bs[k][tx * 4];
                float b[4] = {bv.x, bv.y, bv.z, bv.w};
                float4 a0l = *(float4*)&As[0][k][ty * 8];
                float4 a0h = *(float4*)&As[0][k][ty * 8 + 4];
                float a0[8] = {a0l.x, a0l.y, a0l.z, a0l.w, a0h.x, a0h.y, a0h.z, a0h.w};
#pragma unroll
                for (int i = 0; i < 8; i++)
#pragma unroll
                    for (int j = 0; j < 4; j++)
                        acc[i][j] += a0[i] * b[j];
            }
        }
    }
#pragma unroll
    for (int i = 0; i < 8; i++) {
        size_t r = (size_t)(n0 + ty * 8 + i);
        float4 v = make_float4(acc[i][0], acc[i][1], acc[i][2], acc[i][3]);
        *(float4*)&g_agg[r * 1088 + col0 + tx * 4] = v;
    }
}

// ------------------------- finalize: x1 += agg1+mix1 ; x2 += agg2+mix2 -------------------------
__global__ void finalize_kernel()
{
    const int total = Nn * 544;
    for (int i = blockIdx.x * blockDim.x + threadIdx.x; i < total; i += gridDim.x * blockDim.x) {
        int n = i / 544, t = i % 544;
        if (t < 384) {
            int d = t / 3, c = t % 3;
            g_x1[n * 384 + t] += g_agg[(size_t)n * 1088 + t] + g_agg[(size_t)n * 1088 + 544 + c * 128 + d];
        } else {
            int tt = t - 384, e = tt / 5, c = tt % 5;
            g_x2[n * 160 + tt] += g_agg[(size_t)n * 1088 + 384 + tt] + g_agg[(size_t)n * 1088 + 928 + c * 32 + e];
        }
    }
}

// ------------------------- reduce split-K partials into x0 -------------------------
__global__ void reduce_part_kernel()
{
    const int T = Nn * D0;
    for (int i = blockIdx.x * blockDim.x + threadIdx.x; i < T; i += gridDim.x * blockDim.x)
        g_x0[i] += g_part[i] + g_part[T + i] + g_part[2 * T + i] + g_part[3 * T + i];
}

// ------------------------- apply gate -------------------------
__global__ void gate_kernel()
{
    const int total = Nn * 544;
    for (int i = blockIdx.x * blockDim.x + threadIdx.x; i < total; i += gridDim.x * blockDim.x) {
        int n = i / 544, t = i % 544;
        if (t < 384) g_x1[n * 384 + t] *= g_gate[n * 160 + t / 3];
        else { int tt = t - 384; g_x2[n * 160 + tt] *= g_gate[n * 160 + 128 + tt / 5]; }
    }
}

// ------------------------- zero x1/x2 -------------------------
__global__ void zero_kernel()
{
    const int t1 = Nn * 384, total = Nn * 384 + Nn * 160;
    for (int i = blockIdx.x * blockDim.x + threadIdx.x; i < total; i += gridDim.x * blockDim.x) {
        if (i < t1) g_x1[i] = 0.f; else g_x2[i - t1] = 0.f;
    }
}

// ------------------------- host launcher -------------------------
static inline void launch_gemm(const float* A, const float* B, float* C, const float* bias,
                               int M, int N, int K, int lda, int ldb, int ldc,
                               int act, int accum,
                               int gz = 1, int zdiv = 1,
                               size_t sA1 = 0, size_t sA2 = 0, size_t sB1 = 0, size_t sB2 = 0,
                               size_t sC1 = 0, size_t sC2 = 0)
{
    dim3 grid((N + 63) / 64, (M + 63) / 64, gz);
    gemm_f32<<<grid, 256>>>(A, B, C, bias, M, N, K, lda, ldb, ldc, act, accum, zdiv,
                            sA1, sA2, sB1, sB2, sC1, sC2);
}

extern "C" void kernel_launch(void* const* d_in, const int* in_sizes, int n_in,
                              void* d_out, int out_size)
{
    const float* x     = (const float*)d_in[0];
    const float* pos   = (const float*)d_in[1];
    const float* emb_W = (const float*)d_in[2];
    const float* emb_b = (const float*)d_in[3];
    const float* Wq    = (const float*)d_in[4];
    const float* Wk    = (const float*)d_in[5];
    const float* Wv0   = (const float*)d_in[6];
    const float* Wv1   = (const float*)d_in[7];
    const float* Wv2   = (const float*)d_in[8];
    const float* Ws1   = (const float*)d_in[9];
    const float* Ws2   = (const float*)d_in[10];
    const float* Wffa  = (const float*)d_in[11];
    const float* Wffb  = (const float*)d_in[12];
    const float* Wg    = (const float*)d_in[13];
    const float* out_W = (const float*)d_in[14];
    const float* out_b = (const float*)d_in[15];
    float* out = (float*)d_out;

    void* vp;
    cudaGetSymbolAddress(&vp, g_x0);   float* px0   = (float*)vp;
    cudaGetSymbolAddress(&vp, g_inv);  float* pinv  = (float*)vp;
    cudaGetSymbolAddress(&vp, g_q);    float* pq    = (float*)vp;
    cudaGetSymbolAddress(&vp, g_k);    float* pk    = (float*)vp;
    cudaGetSymbolAddress(&vp, g_attn); float* pattn = (float*)vp;
    cudaGetSymbolAddress(&vp, g_V);    float* pV    = (float*)vp;
    cudaGetSymbolAddress(&vp, g_v0);   float* pv0   = (float*)vp;
    cudaGetSymbolAddress(&vp, g_ff);   float* pff   = (float*)vp;
    cudaGetSymbolAddress(&vp, g_gate); float* pgate = (float*)vp;
    cudaGetSymbolAddress(&vp, g_part); float* ppart = (float*)vp;

    zero_kernel<<<512, 256>>>();
    // x0 = x @ emb_W + emb_b  (K=118 -> scalar path)
    launch_gemm(x, emb_W, px0, emb_b, Nn, D0, 118, 118, D0, D0, 0, 0);

    for (int l = 0; l < NL; l++) {
        const float* Wq_l   = Wq   + (size_t)l * Ff * D0;
        const float* Wk_l   = Wk   + (size_t)l * Ff * D0;
        const float* Wv0_l  = Wv0  + (size_t)l * D0 * D0;
        const float* Wv1_l  = Wv1  + (size_t)l * D1 * D1;
        const float* Wv2_l  = Wv2  + (size_t)l * D2 * D2;
        const float* Ws1_l  = Ws1  + (size_t)l * D0 * D1;
        const float* Ws2_l  = Ws2  + (size_t)l * D0 * D2;
        const float* Wffa_l = Wffa + (size_t)l * D0 * 512;
        const float* Wffb_l = Wffb + (size_t)l * 512 * D0;
        const float* Wg_l   = Wg   + (size_t)l * Ff * 160;

        invariants_kernel<<<1024, 256>>>();
        launch_gemm(pinv, Wq_l, pq, nullptr, Nn, D0, Ff, Ff, D0, D0, 0, 0);
        launch_gemm(pinv, Wk_l, pk, nullptr, Nn, D0, Ff, Ff, D0, D0, 0, 0);
        launch_gemm(px0, Wv0_l, pv0, nullptr, Nn, D0, D0, D0, D0, D0, 0, 0);
        launch_gemm(px0, Ws1_l, pV + 544, nullptr, Nn, D1, D0, D0, D1, 704, 0, 0);
        launch_gemm(px0, Ws2_l, pV + 672, nullptr, Nn, D2, D0, D0, D2, 704, 0, 0);
        v1_kernel<<<Nn, 128>>>(Wv1_l);
        v2_kernel<<<Nn, 32>>>(Wv2_l);

        attn_logits_kernel<<<dim3(32, 32, 4), 256>>>(pq, pk);
        softmax_kernel<<<dim3(Nn, Hh), 256>>>();
        build_w_kernel<<<4096, 256>>>(pos);

        // x0 += attn_h @ v0_h : z = 16 (4 heads x 4 K-splits), partials then reduce
        launch_gemm(pattn, pv0, ppart, nullptr,
                    Nn, DHh, 512, Nn, D0, D0, 0, 0,
                    /*gz=*/16, /*zdiv=*/4,
                    /*sA1=*/NNsz, /*sA2=*/512,
                    /*sB1=*/DHh, /*sB2=*/(size_t)512 * D0,
                    /*sC1=*/DHh, /*sC2=*/(size_t)Nn * D0);
        reduce_part_kernel<<<1024, 256>>>();

        aggmix_kernel<<<dim3(17, 16), 256>>>();
        finalize_kernel<<<1024, 256>>>();

        // feedforward: x0 += silu(x0 @ Wffa) @ Wffb
        launch_gemm(px0, Wffa_l, pff, nullptr, Nn, 512, D0, D0, 512, 512, 1, 0);
        launch_gemm(pff, Wffb_l, px0, nullptr, Nn, D0, 512, 512, D0, D0, 0, 1);

        // gate
        invariants_kernel<<<1024, 256>>>();
        launch_gemm(pinv, Wg_l, pgate, nullptr, Nn, 160, Ff, Ff, 160, 160, 2, 0);
        gate_kernel<<<1024, 256>>>();
    }

    // out = x0 @ out_W + out_b
    launch_gemm(px0, out_W, out, out_b, Nn, NCLS, D0, D0, NCLS, NCLS, 0, 0);
}

// round 3
// speedup vs baseline: 3.4806x; 2.1408x over previous
#include <cuda_runtime.h>
#include <cuda_pipeline.h>
#include <math.h>

#define Nn 2048
#define D0 256
#define D1 128
#define D2 32
#define Hh 4
#define DHh 64
#define Ff 416
#define NCLS 10
#define NL 4
#define SQRT3 1.7320508075688772f
#define NNsz ((size_t)Nn * Nn)
#define VW 1120   // g_V row width: [v1(384)|v2(160)|v0(256)|s1(128)|s2(32)|pad(160)]

typedef unsigned long long u64;

__device__ __forceinline__ u64 pack2(float x) {
    u64 r; asm("mov.b64 %0, {%1, %1};" : "=l"(r) : "f"(x)); return r;
}
__device__ __forceinline__ void fma2(u64& d, u64 a, u64 b) {
    asm("fma.rn.f32x2 %0, %1, %2, %0;" : "+l"(d) : "l"(a), "l"(b));
}
__device__ __forceinline__ float2 unpack2(u64 v) {
    float2 f; asm("mov.b64 {%0, %1}, %2;" : "=f"(f.x), "=f"(f.y) : "l"(v)); return f;
}

// ------------------------- device scratch -------------------------
__device__ float g_x0[Nn * D0];
__device__ float g_x1[Nn * D1 * 3];
__device__ float g_x2[Nn * D2 * 5];
__device__ float g_inv[Nn * Ff];
__device__ float g_qk[Nn * 512];
__device__ float g_attn[(size_t)Hh * Nn * Nn];
__device__ float g_a[NNsz];
__device__ float g_W[8 * NNsz];
__device__ float g_V[Nn * VW];
__device__ float g_agg[Nn * 1088];
__device__ float g_ff[Nn * 512];
__device__ float g_gate[Nn * 160];
__device__ float g_part[4 * Nn * D0];
__device__ float g_qkpack[NL * 416 * 512];
__device__ float g_vpack[NL * 256 * 448];
__device__ float g_gpack[NL * 416 * 192];
__device__ float g_opack[256 * 64];

// ------------------------- pack weights -------------------------
__global__ void pack_kernel(const float* __restrict__ Wq, const float* __restrict__ Wk,
                            const float* __restrict__ Wv0, const float* __restrict__ Ws1,
                            const float* __restrict__ Ws2, const float* __restrict__ Wg,
                            const float* __restrict__ outW)
{
    const int R1 = NL * 416 * 512, R2 = NL * 256 * 448, R3 = NL * 416 * 192, R4 = 256 * 64;
    const int total = R1 + R2 + R3 + R4;
    for (int i = blockIdx.x * blockDim.x + threadIdx.x; i < total; i += gridDim.x * blockDim.x) {
        if (i < R1) {
            int l = i / (416 * 512), rem = i % (416 * 512), f = rem / 512, c = rem % 512;
            g_qkpack[i] = (c < 256) ? Wq[((size_t)l * 416 + f) * 256 + c]
                                    : Wk[((size_t)l * 416 + f) * 256 + (c - 256)];
        } else if (i < R1 + R2) {
            int j = i - R1;
            int l = j / (256 * 448), rem = j % (256 * 448), d = rem / 448, c = rem % 448;
            float v = 0.f;
            if (c < 256)       v = Wv0[((size_t)l * 256 + d) * 256 + c];
            else if (c < 384)  v = Ws1[((size_t)l * 256 + d) * 128 + (c - 256)];
            else if (c < 416)  v = Ws2[((size_t)l * 256 + d) * 32 + (c - 384)];
            g_vpack[j] = v;
        } else if (i < R1 + R2 + R3) {
            int j = i - R1 - R2;
            int l = j / (416 * 192), rem = j % (416 * 192), f = rem / 192, c = rem % 192;
            g_gpack[j] = (c < 160) ? Wg[((size_t)l * 416 + f) * 160 + c] : 0.f;
        } else {
            int j = i - R1 - R2 - R3, d = j / 64, c = j % 64;
            g_opack[j] = (c < 10) ? outW[d * 10 + c] : 0.f;
        }
    }
}

// ------------------------- generic tiled fp32 GEMM v3 (cp.async + f32x2) -------------------------
__device__ __forceinline__ void gemm_compute32(const float (*As)[36], const float (*Bs)[72],
                                               int tx, int ty, u64 acc2[4][2])
{
#pragma unroll
    for (int k = 0; k < 32; k++) {
        u64 b0 = *(const u64*)&Bs[k][tx * 4];
        u64 b1 = *(const u64*)&Bs[k][tx * 4 + 2];
#pragma unroll
        for (int i = 0; i < 4; i++) {
            u64 a2 = pack2(As[ty * 4 + i][k]);
            fma2(acc2[i][0], a2, b0);
            fma2(acc2[i][1], a2, b1);
        }
    }
}

__global__ __launch_bounds__(256)
void gemm_f32(const float* __restrict__ A, const float* __restrict__ B,
              float* __restrict__ C, const float* __restrict__ bias,
              int M, int Ncol, int K, int lda, int ldb, int ldc,
              int act, int accum, int zdiv,
              size_t sA1, size_t sA2, size_t sB1, size_t sB2, size_t sC1, size_t sC2)
{
    int z1 = blockIdx.z % zdiv, z2 = blockIdx.z / zdiv;
    A += (size_t)z1 * sA1 + (size_t)z2 * sA2;
    B += (size_t)z1 * sB1 + (size_t)z2 * sB2;
    C += (size_t)z1 * sC1 + (size_t)z2 * sC2;

    __shared__ float As[2][64][36];
    __shared__ float Bs[2][32][72];
    int tid = threadIdx.x, tx = tid & 15, ty = tid >> 4;
    int row0 = blockIdx.y * 64, col0 = blockIdx.x * 64;
    int nc = (K + 31) >> 5;
    bool fast = ((K & 31) == 0);

    u64 acc2[4][2] = {};

    if (fast) {
        // prologue
        {
#pragma unroll
            for (int t = 0; t < 2; t++) {
                int f2 = tid + t * 256;
                int r = f2 >> 3, k4 = (f2 & 7) * 4;
                __pipeline_memcpy_async(&As[0][r][k4], &A[(size_t)(row0 + r) * lda + k4], 16);
            }
#pragma unroll
            for (int t = 0; t < 2; t++) {
                int f2 = tid + t * 256;
                int k = f2 >> 4, c4 = (f2 & 15) * 4;
                __pipeline_memcpy_async(&Bs[0][k][c4], &B[(size_t)k * ldb + col0 + c4], 16);
            }
            __pipeline_commit();
        }
        for (int c = 0; c < nc; c++) {
            __pipeline_wait_prior(0);
            __syncthreads();
            if (c + 1 < nc) {
                int s = (c + 1) & 1, kk = (c + 1) * 32;
#pragma unroll
                for (int t = 0; t < 2; t++) {
                    int f2 = tid + t * 256;
                    int r = f2 >> 3, k4 = (f2 & 7) * 4;
                    __pipeline_memcpy_async(&As[s][r][k4], &A[(size_t)(row0 + r) * lda + kk + k4], 16);
                }
#pragma unroll
                for (int t = 0; t < 2; t++) {
                    int f2 = tid + t * 256;
                    int k = f2 >> 4, c4 = (f2 & 15) * 4;
                    __pipeline_memcpy_async(&Bs[s][k][c4], &B[(size_t)(kk + k) * ldb + col0 + c4], 16);
                }
                __pipeline_commit();
            }
            gemm_compute32(As[c & 1], Bs[c & 1], tx, ty, acc2);
        }
    } else {
        for (int c = 0; c < nc; c++) {
            __syncthreads();
            for (int i = tid; i < 64 * 32; i += 256) {
                int r = i >> 5, k = i & 31, kg = c * 32 + k;
                As[0][r][k] = (kg < K) ? A[(size_t)(row0 + r) * lda + kg] : 0.f;
            }
            for (int i = tid; i < 32 * 64; i += 256) {
                int k = i >> 6, cc = i & 63, kg = c * 32 + k;
                float v = 0.f;
                if (kg < K && col0 + cc < Ncol) v = B[(size_t)kg * ldb + col0 + cc];
                Bs[0][k][cc] = v;
            }
            __syncthreads();
            gemm_compute32(As[0], Bs[0], tx, ty, acc2);
        }
    }

#pragma unroll
    for (int i = 0; i < 4; i++) {
        int r = row0 + ty * 4 + i;
        float va[4];
        float2 p0 = unpack2(acc2[i][0]), p1 = unpack2(acc2[i][1]);
        va[0] = p0.x; va[1] = p0.y; va[2] = p1.x; va[3] = p1.y;
#pragma unroll
        for (int j = 0; j < 4; j++) {
            int c = col0 + tx * 4 + j;
            if (c < Ncol) {
                float v = va[j];
                if (bias) v += bias[c];
                if (act == 1) v = v / (1.f + __expf(-v));
                else if (act == 2) v = 1.f / (1.f + __expf(-v));
                size_t idx = (size_t)r * ldc + c;
                if (accum) C[idx] += v; else C[idx] = v;
            }
        }
    }
}

// ------------------------- attention logits -------------------------
__global__ __launch_bounds__(256)
void attn_logits_kernel(const float* __restrict__ qk)
{
    int h = blockIdx.z;
    int n0 = blockIdx.y * 64, m0 = blockIdx.x * 64;
    __shared__ float Qs[64][68], Ks[64][68];   // [d][row]
    int tid = threadIdx.x;
    for (int i = tid; i < 1024; i += 256) {
        int r = i >> 4, d4 = (i & 15) * 4;
        float4 vq = *(const float4*)&qk[(size_t)(n0 + r) * 512 + h * 64 + d4];
        Qs[d4 + 0][r] = vq.x; Qs[d4 + 1][r] = vq.y; Qs[d4 + 2][r] = vq.z; Qs[d4 + 3][r] = vq.w;
        float4 vk = *(const float4*)&qk[(size_t)(m0 + r) * 512 + 256 + h * 64 + d4];
        Ks[d4 + 0][r] = vk.x; Ks[d4 + 1][r] = vk.y; Ks[d4 + 2][r] = vk.z; Ks[d4 + 3][r] = vk.w;
    }
    __syncthreads();
    int tx = tid & 15, ty = tid >> 4;
    u64 acc2[2][4] = {};
#pragma unroll 8
    for (int d = 0; d < 64; d++) {
        u64 a0 = *(const u64*)&Qs[d][ty * 4];
        u64 a1 = *(const u64*)&Qs[d][ty * 4 + 2];
#pragma unroll
        for (int j = 0; j < 4; j++) {
            u64 b2 = pack2(Ks[d][tx * 4 + j]);
            fma2(acc2[0][j], a0, b2);
            fma2(acc2[1][j], a1, b2);
        }
    }
#pragma unroll
    for (int ip = 0; ip < 2; ip++) {
        float2 c0 = unpack2(acc2[ip][0]), c1 = unpack2(acc2[ip][1]);
        float2 c2 = unpack2(acc2[ip][2]), c3 = unpack2(acc2[ip][3]);
        size_t base0 = ((size_t)h * Nn + n0 + ty * 4 + 2 * ip) * Nn + m0 + tx * 4;
        float4 rlo = make_float4(c0.x * 0.125f, c1.x * 0.125f, c2.x * 0.125f, c3.x * 0.125f);
        float4 rhi = make_float4(c0.y * 0.125f, c1.y * 0.125f, c2.y * 0.125f, c3.y * 0.125f);
        *(float4*)&g_attn[base0] = rlo;
        *(float4*)&g_attn[base0 + Nn] = rhi;
    }
}

// ------------------------- row softmax -------------------------
__global__ __launch_bounds__(256)
void softmax_kernel()
{
    int n = blockIdx.x, h = blockIdx.y;
    float* p = g_attn + ((size_t)h * Nn + n) * Nn;
    __shared__ float row[Nn];
    __shared__ float red[256];
    int tid = threadIdx.x;

    float mx = -1e30f;
    for (int i = tid * 4; i < Nn; i += 1024) {
        float4 v = *(const float4*)&p[i];
        *(float4*)&row[i] = v;
        mx = fmaxf(mx, fmaxf(fmaxf(v.x, v.y), fmaxf(v.z, v.w)));
    }
    red[tid] = mx; __syncthreads();
    for (int s = 128; s > 0; s >>= 1) { if (tid < s) red[tid] = fmaxf(red[tid], red[tid + s]); __syncthreads(); }
    float m = red[0];
    __syncthreads();

    float sum = 0.f;
    for (int i = tid; i < Nn; i += 256) { float e = __expf(row[i] - m); row[i] = e; sum += e; }
    red[tid] = sum; __syncthreads();
    for (int s = 128; s > 0; s >>= 1) { if (tid < s) red[tid] += red[tid + s]; __syncthreads(); }
    float inv = 1.f / red[0];
    __syncthreads();

    for (int i = tid * 4; i < Nn; i += 1024) {
        float4 v = *(float4*)&row[i];
        v.x *= inv; v.y *= inv; v.z *= inv; v.w *= inv;
        *(float4*)&p[i] = v;
    }
}

// ------------------------- build class weight matrices -------------------------
__global__ void build_w_kernel(const float* __restrict__ pos)
{
    for (size_t q = (size_t)blockIdx.x * blockDim.x + threadIdx.x; q < NNsz / 4;
         q += (size_t)gridDim.x * blockDim.x) {
        size_t i4 = q * 4;
        int n = (int)(i4 >> 11), m = (int)(i4 & 2047);
        float4 h0 = *(const float4*)&g_attn[i4];
        float4 h1 = *(const float4*)&g_attn[NNsz + i4];
        float4 h2 = *(const float4*)&g_attn[2 * NNsz + i4];
        float4 h3 = *(const float4*)&g_attn[3 * NNsz + i4];
        float av[4] = {0.25f * (h0.x + h1.x + h2.x + h3.x), 0.25f * (h0.y + h1.y + h2.y + h3.y),
                       0.25f * (h0.z + h1.z + h2.z + h3.z), 0.25f * (h0.w + h1.w + h2.w + h3.w)};
        float pnx = pos[n * 3 + 0], pny = pos[n * 3 + 1], pnz = pos[n * 3 + 2];
        float o[9][4];
#pragma unroll
        for (int t = 0; t < 4; t++) {
            float a = av[t];
            float rx = pos[(m + t) * 3 + 0] - pnx;
            float ry = pos[(m + t) * 3 + 1] - pny;
            float rz = pos[(m + t) * 3 + 2] - pnz;
            float r2 = rx * rx + ry * ry + rz * rz;
            bool ok = r2 > 1e-12f;
            float inv = ok ? rsqrtf(r2) : 0.f;
            float valid = ok ? 1.f : 0.f;
            float ux = rx * inv, uy = ry * inv, uz = rz * inv;
            o[0][t] = a;
            o[1][t] = a * ux;
            o[2][t] = a * uy;
            o[3][t] = a * uz;
            o[4][t] = a * (SQRT3 * ux * uy);
            o[5][t] = a * (SQRT3 * uy * uz);
            o[6][t] = a * (0.5f * (3.f * uz * uz - 1.f)) * valid;
            o[7][t] = a * (SQRT3 * ux * uz);
            o[8][t] = a * (0.5f * SQRT3 * (ux * ux - uy * uy));
        }
        *(float4*)&g_a[i4] = make_float4(o[0][0], o[0][1], o[0][2], o[0][3]);
#pragma unroll
        for (int c = 0; c < 8; c++)
            *(float4*)&g_W[c * NNsz + i4] = make_float4(o[c + 1][0], o[c + 1][1], o[c + 1][2], o[c + 1][3]);
    }
}

// ------------------------- invariants -------------------------
__global__ void invariants_kernel()
{
    const int total = Nn * Ff;
    for (int i = blockIdx.x * blockDim.x + threadIdx.x; i < total; i += gridDim.x * blockDim.x) {
        int n = i / Ff, c = i % Ff;
        float v;
        if (c < D0) v = g_x0[n * D0 + c];
        else if (c < D0 + D1) {
            const float* p = &g_x1[(n * D1 + (c - D0)) * 3];
            v = sqrtf(p[0] * p[0] + p[1] * p[1] + p[2] * p[2]);
        } else {
            const float* p = &g_x2[(n * D2 + (c - D0 - D1)) * 5];
            v = sqrtf(p[0] * p[0] + p[1] * p[1] + p[2] * p[2] + p[3] * p[3] + p[4] * p[4]);
        }
        g_inv[i] = v;
    }
}

// ------------------------- v1/v2 channel mixes -------------------------
__global__ __launch_bounds__(128)
void v1_kernel(const float* __restrict__ Wv1)
{
    int m = blockIdx.x;
    __shared__ float sx[D1 * 3];
    int tid = threadIdx.x;
    for (int i = tid; i < D1 * 3; i += 128) sx[i] = g_x1[m * D1 * 3 + i];
    __syncthreads();
    float a0 = 0.f, a1 = 0.f, a2 = 0.f;
#pragma unroll 8
    for (int d = 0; d < D1; d++) {
        float w = Wv1[d * D1 + tid];
        a0 += sx[d * 3 + 0] * w;
        a1 += sx[d * 3 + 1] * w;
        a2 += sx[d * 3 + 2] * w;
    }
    float* o = &g_V[(size_t)m * VW + tid * 3];
    o[0] = a0; o[1] = a1; o[2] = a2;
}

__global__ __launch_bounds__(32)
void v2_kernel(const float* __restrict__ Wv2)
{
    int m = blockIdx.x;
    __shared__ float sx[D2 * 5];
    int tid = threadIdx.x;
    for (int i = tid; i < D2 * 5; i += 32) sx[i] = g_x2[m * D2 * 5 + i];
    __syncthreads();
    float a[5] = {};
#pragma unroll 8
    for (int d = 0; d < D2; d++) {
        float w = Wv2[d * D2 + tid];
#pragma unroll
        for (int c = 0; c < 5; c++) a[c] += sx[d * 5 + c] * w;
    }
#pragma unroll
    for (int c = 0; c < 5; c++) g_V[(size_t)m * VW + 384 + tid * 5 + c] = a[c];
}

// ------------------------- fused agg/mix GEMM -------------------------
// g_V row layout: [v1 0..383 | v2 384..543 | v0 544..799 | s1 800..927 | s2 928..959]
// out cols: [0,544): class 0, vcol=col ; [544,928): class 1+(col-544)/128, vcol=800+(col-544)%128
//           [928,1088): class 4+(col-928)/32, vcol=928+(col-928)%32
__device__ __forceinline__ int colcls(int col) {
    return col < 544 ? 0 : (col < 928 ? 1 + ((col - 544) >> 7) : 4 + ((col - 928) >> 5));
}
__device__ __forceinline__ int colv(int col) {
    return col < 544 ? col : (col < 928 ? 800 + ((col - 544) & 127) : 928 + ((col - 928) & 31));
}

#define AGG_AS(s, cls, r, k) dsm[((((s) * 2 + (cls)) * 128 + (r)) * 20) + (k)]
#define AGG_BS(s, k, c) dsm[20480 + ((s) * 16 + (k)) * 72 + (c)]
#define AGG_SMEM ((20480 + 2 * 16 * 72) * 4)

__global__ __launch_bounds__(256)
void aggmix_kernel()
{
    extern __shared__ float dsm[];
    int tid = threadIdx.x, tx = tid & 15, ty = tid >> 4;
    int n0 = blockIdx.y * 128;
    int col0 = blockIdx.x * 64;
    int clsA = colcls(col0);
    int clsB = colcls(col0 + 63);
    bool two = (clsB != clsA);
    const float* WA = (clsA == 0) ? g_a : g_W + (size_t)(clsA - 1) * NNsz;
    const float* WB = (clsB == 0) ? g_a : g_W + (size_t)(clsB - 1) * NNsz;

    // this thread's 4 output cols are single-class (boundaries are multiples of 16)
    int clsT = (colcls(col0 + tx * 4) == clsA) ? 0 : 1;
    // B load mapping: this thread loads the float4 at columns col0 + (tid&15)*4 for k-row tid>>4
    int kB = tid >> 4, c4 = (tid & 15) * 4;
    int vcol = colv(col0 + c4);

    u64 acc2[8][2] = {};

    // prologue: chunk 0 -> stage 0
    {
        __pipeline_memcpy_async(&AGG_BS(0, kB, c4), &g_V[(size_t)kB * VW + vcol], 16);
#pragma unroll
        for (int t = 0; t < 2; t++) {
            int f2 = tid + t * 256;
            int r = f2 >> 2, k4 = (f2 & 3) * 4;
            __pipeline_memcpy_async(&AGG_AS(0, 0, r, k4), &WA[(size_t)(n0 + r) * Nn + k4], 16);
        }
        if (two) {
#pragma unroll
            for (int t = 0; t < 2; t++) {
                int f2 = tid + t * 256;
                int r = f2 >> 2, k4 = (f2 & 3) * 4;
                __pipeline_memcpy_async(&AGG_AS(0, 1, r, k4), &WB[(size_t)(n0 + r) * Nn + k4], 16);
            }
        }
        __pipeline_commit();
    }

    const int NCHUNK = Nn / 16;
    for (int c = 0; c < NCHUNK; c++) {
        __pipeline_wait_prior(0);
        __syncthreads();
        if (c + 1 < NCHUNK) {
            int s = (c + 1) & 1, kk = (c + 1) * 16;
            __pipeline_memcpy_async(&AGG_BS(s, kB, c4), &g_V[(size_t)(kk + kB) * VW + vcol], 16);
#pragma unroll
            for (int t = 0; t < 2; t++) {
                int f2 = tid + t * 256;
                int r = f2 >> 2, k4 = (f2 & 3) * 4;
                __pipeline_memcpy_async(&AGG_AS(s, 0, r, k4), &WA[(size_t)(n0 + r) * Nn + kk + k4], 16);
            }
            if (two) {
#pragma unroll
                for (int t = 0; t < 2; t++) {
                    int f2 = tid + t * 256;
                    int r = f2 >> 2, k4 = (f2 & 3) * 4;
                    __pipeline_memcpy_async(&AGG_AS(s, 1, r, k4), &WB[(size_t)(n0 + r) * Nn + kk + k4], 16);
                }
            }
            __pipeline_commit();
        }
        int buf = c & 1;
#pragma unroll
        for (int k = 0; k < 16; k++) {
            u64 b0 = *(const u64*)&AGG_BS(buf, k, tx * 4);
            u64 b1 = *(const u64*)&AGG_BS(buf, k, tx * 4 + 2);
#pragma unroll
            for (int i = 0; i < 8; i++) {
                u64 a2 = pack2(AGG_AS(buf, clsT, ty * 8 + i, k));
                fma2(acc2[i][0], a2, b0);
                fma2(acc2[i][1], a2, b1);
            }
        }
    }

#pragma unroll
    for (int i = 0; i < 8; i++) {
        size_t r = (size_t)(n0 + ty * 8 + i);
        float2 p0 = unpack2(acc2[i][0]), p1 = unpack2(acc2[i][1]);
        *(float4*)&g_agg[r * 1088 + col0 + tx * 4] = make_float4(p0.x, p0.y, p1.x, p1.y);
    }
}

// ------------------------- finalize / reduce / gate / zero -------------------------
__global__ void finalize_kernel()
{
    const int total = Nn * 544;
    for (int i = blockIdx.x * blockDim.x + threadIdx.x; i < total; i += gridDim.x * blockDim.x) {
        int n = i / 544, t = i % 544;
        if (t < 384) {
            int d = t / 3, c = t % 3;
            g_x1[n * 384 + t] += g_agg[(size_t)n * 1088 + t] + g_agg[(size_t)n * 1088 + 544 + c * 128 + d];
        } else {
            int tt = t - 384, e = tt / 5, c = tt % 5;
            g_x2[n * 160 + tt] += g_agg[(size_t)n * 1088 + 384 + tt] + g_agg[(size_t)n * 1088 + 928 + c * 32 + e];
        }
    }
}

__global__ void reduce_part_kernel()
{
    const int T = Nn * D0;
    for (int i = blockIdx.x * blockDim.x + threadIdx.x; i < T; i += gridDim.x * blockDim.x)
        g_x0[i] += g_part[i] + g_part[T + i] + g_part[2 * T + i] + g_part[3 * T + i];
}

__global__ void gate_kernel()
{
    const int total = Nn * 544;
    for (int i = blockIdx.x * blockDim.x + threadIdx.x; i < total; i += gridDim.x * blockDim.x) {
        int n = i / 544, t = i % 544;
        if (t < 384) g_x1[n * 384 + t] *= g_gate[n * 160 + t / 3];
        else { int tt = t - 384; g_x2[n * 160 + tt] *= g_gate[n * 160 + 128 + tt / 5]; }
    }
}

__global__ void zero_kernel()
{
    const int t1 = Nn * 384, total = Nn * 384 + Nn * 160;
    for (int i = blockIdx.x * blockDim.x + threadIdx.x; i < total; i += gridDim.x * blockDim.x) {
        if (i < t1) g_x1[i] = 0.f; else g_x2[i - t1] = 0.f;
    }
}

// ------------------------- host launcher -------------------------
static inline void launch_gemm(const float* A, const float* B, float* C, const float* bias,
                               int M, int N, int K, int lda, int ldb, int ldc,
                               int act, int accum,
                               int gz = 1, int zdiv = 1,
                               size_t sA1 = 0, size_t sA2 = 0, size_t sB1 = 0, size_t sB2 = 0,
                               size_t sC1 = 0, size_t sC2 = 0)
{
    dim3 grid((N + 63) / 64, (M + 63) / 64, gz);
    gemm_f32<<<grid, 256>>>(A, B, C, bias, M, N, K, lda, ldb, ldc, act, accum, zdiv,
                            sA1, sA2, sB1, sB2, sC1, sC2);
}

extern "C" void kernel_launch(void* const* d_in, const int* in_sizes, int n_in,
                              void* d_out, int out_size)
{
    const float* x     = (const float*)d_in[0];
    const float* pos   = (const float*)d_in[1];
    const float* emb_W = (const float*)d_in[2];
    const float* emb_b = (const float*)d_in[3];
    const float* Wq    = (const float*)d_in[4];
    const float* Wk    = (const float*)d_in[5];
    const float* Wv0   = (const float*)d_in[6];
    const float* Wv1   = (const float*)d_in[7];
    const float* Wv2   = (const float*)d_in[8];
    const float* Ws1   = (const float*)d_in[9];
    const float* Ws2   = (const float*)d_in[10];
    const float* Wffa  = (const float*)d_in[11];
    const float* Wffb  = (const float*)d_in[12];
    const float* Wg    = (const float*)d_in[13];
    const float* out_W = (const float*)d_in[14];
    const float* out_b = (const float*)d_in[15];
    float* out = (float*)d_out;

    static int smem_set = 0;
    if (!smem_set) {
        cudaFuncSetAttribute(aggmix_kernel, cudaFuncAttributeMaxDynamicSharedMemorySize, AGG_SMEM);
        smem_set = 1;
    }

    void* vp;
    cudaGetSymbolAddress(&vp, g_x0);     float* px0   = (float*)vp;
    cudaGetSymbolAddress(&vp, g_inv);    float* pinv  = (float*)vp;
    cudaGetSymbolAddress(&vp, g_qk);     float* pqk   = (float*)vp;
    cudaGetSymbolAddress(&vp, g_attn);   float* pattn = (float*)vp;
    cudaGetSymbolAddress(&vp, g_V);      float* pV    = (float*)vp;
    cudaGetSymbolAddress(&vp, g_ff);     float* pff   = (float*)vp;
    cudaGetSymbolAddress(&vp, g_gate);   float* pgate = (float*)vp;
    cudaGetSymbolAddress(&vp, g_part);   float* ppart = (float*)vp;
    cudaGetSymbolAddress(&vp, g_qkpack); float* pqkp  = (float*)vp;
    cudaGetSymbolAddress(&vp, g_vpack);  float* pvp   = (float*)vp;
    cudaGetSymbolAddress(&vp, g_gpack);  float* pgp   = (float*)vp;
    cudaGetSymbolAddress(&vp, g_opack);  float* pop   = (float*)vp;

    pack_kernel<<<2048, 256>>>(Wq, Wk, Wv0, Ws1, Ws2, Wg, out_W);
    zero_kernel<<<512, 256>>>();
    // x0 = x @ emb_W + emb_b  (K=118 -> slow path)
    launch_gemm(x, emb_W, px0, emb_b, Nn, D0, 118, 118, D0, D0, 0, 0);

    for (int l = 0; l < NL; l++) {
        const float* qk_l  = pqkp + (size_t)l * 416 * 512;
        const float* vp_l  = pvp  + (size_t)l * 256 * 448;
        const float* gp_l  = pgp  + (size_t)l * 416 * 192;
        const float* Wv1_l = Wv1  + (size_t)l * D1 * D1;
        const float* Wv2_l = Wv2  + (size_t)l * D2 * D2;
        const float* Wffa_l = Wffa + (size_t)l * D0 * 512;
        const float* Wffb_l = Wffb + (size_t)l * 512 * D0;

        invariants_kernel<<<1024, 256>>>();
        // [q|k] = inv @ [Wq|Wk]
        launch_gemm(pinv, qk_l, pqk, nullptr, Nn, 512, Ff, Ff, 512, 512, 0, 0);
        // [v0|s1|s2] = x0 @ [Wv0|Ws1|Ws2]  -> g_V cols 544..959
        launch_gemm(px0, vp_l, pV + 544, nullptr, Nn, 416, D0, D0, 448, VW, 0, 0);
        v1_kernel<<<Nn, 128>>>(Wv1_l);
        v2_kernel<<<Nn, 32>>>(Wv2_l);

        attn_logits_kernel<<<dim3(32, 32, 4), 256>>>(pqk);
        softmax_kernel<<<dim3(Nn, Hh), 256>>>();
        build_w_kernel<<<4096, 256>>>(pos);

        // x0 += attn_h @ v0_h : 16 z-blocks (4 heads x 4 K-splits)
        launch_gemm(pattn, pV + 544, ppart, nullptr,
                    Nn, DHh, 512, Nn, VW, D0, 0, 0,
                    /*gz=*/16, /*zdiv=*/4,
                    /*sA1=*/NNsz, /*sA2=*/512,
                    /*sB1=*/DHh, /*sB2=*/(size_t)512 * VW,
                    /*sC1=*/DHh, /*sC2=*/(size_t)Nn * D0);
        reduce_part_kernel<<<1024, 256>>>();

        aggmix_kernel<<<dim3(17, 16), 256, AGG_SMEM>>>();
        finalize_kernel<<<1024, 256>>>();

        launch_gemm(px0, Wffa_l, pff, nullptr, Nn, 512, D0, D0, 512, 512, 1, 0);
        launch_gemm(pff, Wffb_l, px0, nullptr, Nn, D0, 512, 512, D0, D0, 0, 1);

        invariants_kernel<<<1024, 256>>>();
        launch_gemm(pinv, gp_l, pgate, nullptr, Nn, 160, Ff, Ff, 192, 160, 2, 0);
        gate_kernel<<<1024, 256>>>();
    }

    launch_gemm(px0, pop, out, out_b, Nn, NCLS, D0, D0, 64, NCLS, 0, 0);
}

// round 4
// speedup vs baseline: 3.4845x; 1.0011x over previous
#include <cuda_runtime.h>
#include <cuda_pipeline.h>
#include <math.h>

#define Nn 2048
#define D0 256
#define D1 128
#define D2 32
#define Hh 4
#define DHh 64
#define Ff 416
#define NCLS 10
#define NL 4
#define SQRT3 1.7320508075688772f
#define NNsz ((size_t)Nn * Nn)
#define VW 1120   // g_V row width: [v1(384)|v2(160)|v0(256)|s1(128)|s2(32)|pad(160)]

typedef unsigned long long u64;

__device__ __forceinline__ u64 pack2(float x) {
    u64 r; asm("mov.b64 %0, {%1, %1};" : "=l"(r) : "f"(x)); return r;
}
__device__ __forceinline__ void fma2(u64& d, u64 a, u64 b) {
    asm("fma.rn.f32x2 %0, %1, %2, %0;" : "+l"(d) : "l"(a), "l"(b));
}
__device__ __forceinline__ float2 unpack2(u64 v) {
    float2 f; asm("mov.b64 {%0, %1}, %2;" : "=f"(f.x), "=f"(f.y) : "l"(v)); return f;
}

// ------------------------- device scratch -------------------------
__device__ float g_x0[Nn * D0];
__device__ float g_x1[Nn * D1 * 3];
__device__ float g_x2[Nn * D2 * 5];
__device__ float g_inv[Nn * Ff];
__device__ float g_qk[Nn * 512];
__device__ float g_attn[(size_t)Hh * Nn * Nn];
__device__ float g_a[NNsz];
__device__ float g_W[8 * NNsz];
__device__ float g_V[Nn * VW];
__device__ float g_agg[Nn * 1088];
__device__ float g_ff[Nn * 512];
__device__ float g_gate[Nn * 160];
__device__ float g_part[4 * Nn * D0];
__device__ float g_qkpack[NL * 416 * 512];
__device__ float g_vpack[NL * 256 * 448];
__device__ float g_gpack[NL * 416 * 192];
__device__ float g_opack[256 * 64];

// ------------------------- pack weights -------------------------
__global__ void pack_kernel(const float* __restrict__ Wq, const float* __restrict__ Wk,
                            const float* __restrict__ Wv0, const float* __restrict__ Ws1,
                            const float* __restrict__ Ws2, const float* __restrict__ Wg,
                            const float* __restrict__ outW)
{
    const int R1 = NL * 416 * 512, R2 = NL * 256 * 448, R3 = NL * 416 * 192, R4 = 256 * 64;
    const int total = R1 + R2 + R3 + R4;
    for (int i = blockIdx.x * blockDim.x + threadIdx.x; i < total; i += gridDim.x * blockDim.x) {
        if (i < R1) {
            int l = i / (416 * 512), rem = i % (416 * 512), f = rem / 512, c = rem % 512;
            g_qkpack[i] = (c < 256) ? Wq[((size_t)l * 416 + f) * 256 + c]
                                    : Wk[((size_t)l * 416 + f) * 256 + (c - 256)];
        } else if (i < R1 + R2) {
            int j = i - R1;
            int l = j / (256 * 448), rem = j % (256 * 448), d = rem / 448, c = rem % 448;
            float v = 0.f;
            if (c < 256)       v = Wv0[((size_t)l * 256 + d) * 256 + c];
            else if (c < 384)  v = Ws1[((size_t)l * 256 + d) * 128 + (c - 256)];
            else if (c < 416)  v = Ws2[((size_t)l * 256 + d) * 32 + (c - 384)];
            g_vpack[j] = v;
        } else if (i < R1 + R2 + R3) {
            int j = i - R1 - R2;
            int l = j / (416 * 192), rem = j % (416 * 192), f = rem / 192, c = rem % 192;
            g_gpack[j] = (c < 160) ? Wg[((size_t)l * 416 + f) * 160 + c] : 0.f;
        } else {
            int j = i - R1 - R2 - R3, d = j / 64, c = j % 64;
            g_opack[j] = (c < 10) ? outW[d * 10 + c] : 0.f;
        }
    }
}

// ------------------------- generic tiled fp32 GEMM v3 (cp.async + f32x2) -------------------------
__device__ __forceinline__ void gemm_compute32(const float (*As)[36], const float (*Bs)[72],
                                               int tx, int ty, u64 acc2[4][2])
{
#pragma unroll
    for (int k = 0; k < 32; k++) {
        u64 b0 = *(const u64*)&Bs[k][tx * 4];
        u64 b1 = *(const u64*)&Bs[k][tx * 4 + 2];
#pragma unroll
        for (int i = 0; i < 4; i++) {
            u64 a2 = pack2(As[ty * 4 + i][k]);
            fma2(acc2[i][0], a2, b0);
            fma2(acc2[i][1], a2, b1);
        }
    }
}

__global__ __launch_bounds__(256)
void gemm_f32(const float* __restrict__ A, const float* __restrict__ B,
              float* __restrict__ C, const float* __restrict__ bias,
              int M, int Ncol, int K, int lda, int ldb, int ldc,
              int act, int accum, int zdiv,
              size_t sA1, size_t sA2, size_t sB1, size_t sB2, size_t sC1, size_t sC2)
{
    int z1 = blockIdx.z % zdiv, z2 = blockIdx.z / zdiv;
    A += (size_t)z1 * sA1 + (size_t)z2 * sA2;
    B += (size_t)z1 * sB1 + (size_t)z2 * sB2;
    C += (size_t)z1 * sC1 + (size_t)z2 * sC2;

    __shared__ float As[2][64][36];
    __shared__ float Bs[2][32][72];
    int tid = threadIdx.x, tx = tid & 15, ty = tid >> 4;
    int row0 = blockIdx.y * 64, col0 = blockIdx.x * 64;
    int nc = (K + 31) >> 5;
    bool fast = ((K & 31) == 0);

    u64 acc2[4][2] = {};

    if (fast) {
        // prologue
        {
#pragma unroll
            for (int t = 0; t < 2; t++) {
                int f2 = tid + t * 256;
                int r = f2 >> 3, k4 = (f2 & 7) * 4;
                __pipeline_memcpy_async(&As[0][r][k4], &A[(size_t)(row0 + r) * lda + k4], 16);
            }
#pragma unroll
            for (int t = 0; t < 2; t++) {
                int f2 = tid + t * 256;
                int k = f2 >> 4, c4 = (f2 & 15) * 4;
                __pipeline_memcpy_async(&Bs[0][k][c4], &B[(size_t)k * ldb + col0 + c4], 16);
            }
            __pipeline_commit();
        }
        for (int c = 0; c < nc; c++) {
            __pipeline_wait_prior(0);
            __syncthreads();
            if (c + 1 < nc) {
                int s = (c + 1) & 1, kk = (c + 1) * 32;
#pragma unroll
                for (int t = 0; t < 2; t++) {
                    int f2 = tid + t * 256;
                    int r = f2 >> 3, k4 = (f2 & 7) * 4;
                    __pipeline_memcpy_async(&As[s][r][k4], &A[(size_t)(row0 + r) * lda + kk + k4], 16);
                }
#pragma unroll
                for (int t = 0; t < 2; t++) {
                    int f2 = tid + t * 256;
                    int k = f2 >> 4, c4 = (f2 & 15) * 4;
                    __pipeline_memcpy_async(&Bs[s][k][c4], &B[(size_t)(kk + k) * ldb + col0 + c4], 16);
                }
                __pipeline_commit();
            }
            gemm_compute32(As[c & 1], Bs[c & 1], tx, ty, acc2);
        }
    } else {
        for (int c = 0; c < nc; c++) {
            __syncthreads();
            for (int i = tid; i < 64 * 32; i += 256) {
                int r = i >> 5, k = i & 31, kg = c * 32 + k;
                As[0][r][k] = (kg < K) ? A[(size_t)(row0 + r) * lda + kg] : 0.f;
            }
            for (int i = tid; i < 32 * 64; i += 256) {
                int k = i >> 6, cc = i & 63, kg = c * 32 + k;
                float v = 0.f;
                if (kg < K && col0 + cc < Ncol) v = B[(size_t)kg * ldb + col0 + cc];
                Bs[0][k][cc] = v;
            }
            __syncthreads();
            gemm_compute32(As[0], Bs[0], tx, ty, acc2);
        }
    }

#pragma unroll
    for (int i = 0; i < 4; i++) {
        int r = row0 + ty * 4 + i;
        float va[4];
        float2 p0 = unpack2(acc2[i][0]), p1 = unpack2(acc2[i][1]);
        va[0] = p0.x; va[1] = p0.y; va[2] = p1.x; va[3] = p1.y;
#pragma unroll
        for (int j = 0; j < 4; j++) {
            int c = col0 + tx * 4 + j;
            if (c < Ncol) {
                float v = va[j];
                if (bias) v += bias[c];
                if (act == 1) v = v / (1.f + __expf(-v));
                else if (act == 2) v = 1.f / (1.f + __expf(-v));
                size_t idx = (size_t)r * ldc + c;
                if (accum) C[idx] += v; else C[idx] = v;
            }
        }
    }
}

// ------------------------- attention logits -------------------------
__global__ __launch_bounds__(256)
void attn_logits_kernel(const float* __restrict__ qk)
{
    int h = blockIdx.z;
    int n0 = blockIdx.y * 64, m0 = blockIdx.x * 64;
    __shared__ float Qs[64][68], Ks[64][68];   // [d][row]
    int tid = threadIdx.x;
    for (int i = tid; i < 1024; i += 256) {
        int r = i >> 4, d4 = (i & 15) * 4;
        float4 vq = *(const float4*)&qk[(size_t)(n0 + r) * 512 + h * 64 + d4];
        Qs[d4 + 0][r] = vq.x; Qs[d4 + 1][r] = vq.y; Qs[d4 + 2][r] = vq.z; Qs[d4 + 3][r] = vq.w;
        float4 vk = *(const float4*)&qk[(size_t)(m0 + r) * 512 + 256 + h * 64 + d4];
        Ks[d4 + 0][r] = vk.x; Ks[d4 + 1][r] = vk.y; Ks[d4 + 2][r] = vk.z; Ks[d4 + 3][r] = vk.w;
    }
    __syncthreads();
    int tx = tid & 15, ty = tid >> 4;
    u64 acc2[2][4] = {};
#pragma unroll 8
    for (int d = 0; d < 64; d++) {
        u64 a0 = *(const u64*)&Qs[d][ty * 4];
        u64 a1 = *(const u64*)&Qs[d][ty * 4 + 2];
#pragma unroll
        for (int j = 0; j < 4; j++) {
            u64 b2 = pack2(Ks[d][tx * 4 + j]);
            fma2(acc2[0][j], a0, b2);
            fma2(acc2[1][j], a1, b2);
        }
    }
#pragma unroll
    for (int ip = 0; ip < 2; ip++) {
        float2 c0 = unpack2(acc2[ip][0]), c1 = unpack2(acc2[ip][1]);
        float2 c2 = unpack2(acc2[ip][2]), c3 = unpack2(acc2[ip][3]);
        size_t base0 = ((size_t)h * Nn + n0 + ty * 4 + 2 * ip) * Nn + m0 + tx * 4;
        float4 rlo = make_float4(c0.x * 0.125f, c1.x * 0.125f, c2.x * 0.125f, c3.x * 0.125f);
        float4 rhi = make_float4(c0.y * 0.125f, c1.y * 0.125f, c2.y * 0.125f, c3.y * 0.125f);
        *(float4*)&g_attn[base0] = rlo;
        *(float4*)&g_attn[base0 + Nn] = rhi;
    }
}

// ------------------------- row softmax -------------------------
__global__ __launch_bounds__(256)
void softmax_kernel()
{
    int n = blockIdx.x, h = blockIdx.y;
    float* p = g_attn + ((size_t)h * Nn + n) * Nn;
    __shared__ float row[Nn];
    __shared__ float red[256];
    int tid = threadIdx.x;

    float mx = -1e30f;
    for (int i = tid * 4; i < Nn; i += 1024) {
        float4 v = *(const float4*)&p[i];
        *(float4*)&row[i] = v;
        mx = fmaxf(mx, fmaxf(fmaxf(v.x, v.y), fmaxf(v.z, v.w)));
    }
    red[tid] = mx; __syncthreads();
    for (int s = 128; s > 0; s >>= 1) { if (tid < s) red[tid] = fmaxf(red[tid], red[tid + s]); __syncthreads(); }
    float m = red[0];
    __syncthreads();

    float sum = 0.f;
    for (int i = tid; i < Nn; i += 256) { float e = __expf(row[i] - m); row[i] = e; sum += e; }
    red[tid] = sum; __syncthreads();
    for (int s = 128; s > 0; s >>= 1) { if (tid < s) red[tid] += red[tid + s]; __syncthreads(); }
    float inv = 1.f / red[0];
    __syncthreads();

    for (int i = tid * 4; i < Nn; i += 1024) {
        float4 v = *(float4*)&row[i];
        v.x *= inv; v.y *= inv; v.z *= inv; v.w *= inv;
        *(float4*)&p[i] = v;
    }
}

// ------------------------- build class weight matrices -------------------------
__global__ void build_w_kernel(const float* __restrict__ pos)
{
    for (size_t q = (size_t)blockIdx.x * blockDim.x + threadIdx.x; q < NNsz / 4;
         q += (size_t)gridDim.x * blockDim.x) {
        size_t i4 = q * 4;
        int n = (int)(i4 >> 11), m = (int)(i4 & 2047);
        float4 h0 = *(const float4*)&g_attn[i4];
        float4 h1 = *(const float4*)&g_attn[NNsz + i4];
        float4 h2 = *(const float4*)&g_attn[2 * NNsz + i4];
        float4 h3 = *(const float4*)&g_attn[3 * NNsz + i4];
        float av[4] = {0.25f * (h0.x + h1.x + h2.x + h3.x), 0.25f * (h0.y + h1.y + h2.y + h3.y),
                       0.25f * (h0.z + h1.z + h2.z + h3.z), 0.25f * (h0.w + h1.w + h2.w + h3.w)};
        float pnx = pos[n * 3 + 0], pny = pos[n * 3 + 1], pnz = pos[n * 3 + 2];
        float o[9][4];
#pragma unroll
        for (int t = 0; t < 4; t++) {
            float a = av[t];
            float rx = pos[(m + t) * 3 + 0] - pnx;
            float ry = pos[(m + t) * 3 + 1] - pny;
            float rz = pos[(m + t) * 3 + 2] - pnz;
            float r2 = rx * rx + ry * ry + rz * rz;
            bool ok = r2 > 1e-12f;
            float inv = ok ? rsqrtf(r2) : 0.f;
            float valid = ok ? 1.f : 0.f;
            float ux = rx * inv, uy = ry * inv, uz = rz * inv;
            o[0][t] = a;
            o[1][t] = a * ux;
            o[2][t] = a * uy;
            o[3][t] = a * uz;
            o[4][t] = a * (SQRT3 * ux * uy);
            o[5][t] = a * (SQRT3 * uy * uz);
            o[6][t] = a * (0.5f * (3.f * uz * uz - 1.f)) * valid;
            o[7][t] = a * (SQRT3 * ux * uz);
            o[8][t] = a * (0.5f * SQRT3 * (ux * ux - uy * uy));
        }
        *(float4*)&g_a[i4] = make_float4(o[0][0], o[0][1], o[0][2], o[0][3]);
#pragma unroll
        for (int c = 0; c < 8; c++)
            *(float4*)&g_W[c * NNsz + i4] = make_float4(o[c + 1][0], o[c + 1][1], o[c + 1][2], o[c + 1][3]);
    }
}

// ------------------------- invariants -------------------------
__global__ void invariants_kernel()
{
    const int total = Nn * Ff;
    for (int i = blockIdx.x * blockDim.x + threadIdx.x; i < total; i += gridDim.x * blockDim.x) {
        int n = i / Ff, c = i % Ff;
        float v;
        if (c < D0) v = g_x0[n * D0 + c];
        else if (c < D0 + D1) {
            const float* p = &g_x1[(n * D1 + (c - D0)) * 3];
            v = sqrtf(p[0] * p[0] + p[1] * p[1] + p[2] * p[2]);
        } else {
            const float* p = &g_x2[(n * D2 + (c - D0 - D1)) * 5];
            v = sqrtf(p[0] * p[0] + p[1] * p[1] + p[2] * p[2] + p[3] * p[3] + p[4] * p[4]);
        }
        g_inv[i] = v;
    }
}

// ------------------------- v1/v2 channel mixes -------------------------
__global__ __launch_bounds__(128)
void v1_kernel(const float* __restrict__ Wv1)
{
    int m = blockIdx.x;
    __shared__ float sx[D1 * 3];
    int tid = threadIdx.x;
    for (int i = tid; i < D1 * 3; i += 128) sx[i] = g_x1[m * D1 * 3 + i];
    __syncthreads();
    float a0 = 0.f, a1 = 0.f, a2 = 0.f;
#pragma unroll 8
    for (int d = 0; d < D1; d++) {
        float w = Wv1[d * D1 + tid];
        a0 += sx[d * 3 + 0] * w;
        a1 += sx[d * 3 + 1] * w;
        a2 += sx[d * 3 + 2] * w;
    }
    float* o = &g_V[(size_t)m * VW + tid * 3];
    o[0] = a0; o[1] = a1; o[2] = a2;
}

__global__ __launch_bounds__(32)
void v2_kernel(const float* __restrict__ Wv2)
{
    int m = blockIdx.x;
    __shared__ float sx[D2 * 5];
    int tid = threadIdx.x;
    for (int i = tid; i < D2 * 5; i += 32) sx[i] = g_x2[m * D2 * 5 + i];
    __syncthreads();
    float a[5] = {};
#pragma unroll 8
    for (int d = 0; d < D2; d++) {
        float w = Wv2[d * D2 + tid];
#pragma unroll
        for (int c = 0; c < 5; c++) a[c] += sx[d * 5 + c] * w;
    }
#pragma unroll
    for (int c = 0; c < 5; c++) g_V[(size_t)m * VW + 384 + tid * 5 + c] = a[c];
}

// ------------------------- fused agg/mix GEMM -------------------------
// g_V row layout: [v1 0..383 | v2 384..543 | v0 544..799 | s1 800..927 | s2 928..959]
// out cols: [0,544): class 0, vcol=col ; [544,928): class 1+(col-544)/128, vcol=800+(col-544)%128
//           [928,1088): class 4+(col-928)/32, vcol=928+(col-928)%32
__device__ __forceinline__ int colcls(int col) {
    return col < 544 ? 0 : (col < 928 ? 1 + ((col - 544) >> 7) : 4 + ((col - 928) >> 5));
}
__device__ __forceinline__ int colv(int col) {
    return col < 544 ? col : (col < 928 ? 800 + ((col - 544) & 127) : 928 + ((col - 928) & 31));
}

#define AGG_AS(s, cls, r, k) dsm[((((s) * 2 + (cls)) * 128 + (r)) * 20) + (k)]
#define AGG_BS(s, k, c) dsm[20480 + ((s) * 16 + (k)) * 72 + (c)]
#define AGG_SMEM ((20480 + 2 * 16 * 72) * 4)

__global__ __launch_bounds__(256)
void aggmix_kernel()
{
    extern __shared__ float dsm[];
    int tid = threadIdx.x, tx = tid & 15, ty = tid >> 4;
    int n0 = blockIdx.y * 128;
    int col0 = blockIdx.x * 64;
    int clsA = colcls(col0);
    int clsB = colcls(col0 + 63);
    bool two = (clsB != clsA);
    const float* WA = (clsA == 0) ? g_a : g_W + (size_t)(clsA - 1) * NNsz;
    const float* WB = (clsB == 0) ? g_a : g_W + (size_t)(clsB - 1) * NNsz;

    // this thread's 4 output cols are single-class (boundaries are multiples of 16)
    int clsT = (colcls(col0 + tx * 4) == clsA) ? 0 : 1;
    // B load mapping: this thread loads the float4 at columns col0 + (tid&15)*4 for k-row tid>>4
    int kB = tid >> 4, c4 = (tid & 15) * 4;
    int vcol = colv(col0 + c4);

    u64 acc2[8][2] = {};

    // prologue: chunk 0 -> stage 0
    {
        __pipeline_memcpy_async(&AGG_BS(0, kB, c4), &g_V[(size_t)kB * VW + vcol], 16);
#pragma unroll
        for (int t = 0; t < 2; t++) {
            int f2 = tid + t * 256;
            int r = f2 >> 2, k4 = (f2 & 3) * 4;
            __pipeline_memcpy_async(&AGG_AS(0, 0, r, k4), &WA[(size_t)(n0 + r) * Nn + k4], 16);
        }
        if (two) {
#pragma unroll
            for (int t = 0; t < 2; t++) {
                int f2 = tid + t * 256;
                int r = f2 >> 2, k4 = (f2 & 3) * 4;
                __pipeline_memcpy_async(&AGG_AS(0, 1, r, k4), &WB[(size_t)(n0 + r) * Nn + k4], 16);
            }
        }
        __pipeline_commit();
    }

    const int NCHUNK = Nn / 16;
    for (int c = 0; c < NCHUNK; c++) {
        __pipeline_wait_prior(0);
        __syncthreads();
        if (c + 1 < NCHUNK) {
            int s = (c + 1) & 1, kk = (c + 1) * 16;
            __pipeline_memcpy_async(&AGG_BS(s, kB, c4), &g_V[(size_t)(kk + kB) * VW + vcol], 16);
#pragma unroll
            for (int t = 0; t < 2; t++) {
                int f2 = tid + t * 256;
                int r = f2 >> 2, k4 = (f2 & 3) * 4;
                __pipeline_memcpy_async(&AGG_AS(s, 0, r, k4), &WA[(size_t)(n0 + r) * Nn + kk + k4], 16);
            }
            if (two) {
#pragma unroll
                for (int t = 0; t < 2; t++) {
                    int f2 = tid + t * 256;
                    int r = f2 >> 2, k4 = (f2 & 3) * 4;
                    __pipeline_memcpy_async(&AGG_AS(s, 1, r, k4), &WB[(size_t)(n0 + r) * Nn + kk + k4], 16);
                }
            }
            __pipeline_commit();
        }
        int buf = c & 1;
#pragma unroll
        for (int k = 0; k < 16; k++) {
            u64 b0 = *(const u64*)&AGG_BS(buf, k, tx * 4);
            u64 b1 = *(const u64*)&AGG_BS(buf, k, tx * 4 + 2);
#pragma unroll
            for (int i = 0; i < 8; i++) {
                u64 a2 = pack2(AGG_AS(buf, clsT, ty * 8 + i, k));
                fma2(acc2[i][0], a2, b0);
                fma2(acc2[i][1], a2, b1);
            }
        }
    }

#pragma unroll
    for (int i = 0; i < 8; i++) {
        size_t r = (size_t)(n0 + ty * 8 + i);
        float2 p0 = unpack2(acc2[i][0]), p1 = unpack2(acc2[i][1]);
        *(float4*)&g_agg[r * 1088 + col0 + tx * 4] = make_float4(p0.x, p0.y, p1.x, p1.y);
    }
}

// ------------------------- finalize / reduce / gate / zero -------------------------
__global__ void finalize_kernel()
{
    const int total = Nn * 544;
    for (int i = blockIdx.x * blockDim.x + threadIdx.x; i < total; i += gridDim.x * blockDim.x) {
        int n = i / 544, t = i % 544;
        if (t < 384) {
            int d = t / 3, c = t % 3;
            g_x1[n * 384 + t] += g_agg[(size_t)n * 1088 + t] + g_agg[(size_t)n * 1088 + 544 + c * 128 + d];
        } else {
            int tt = t - 384, e = tt / 5, c = tt % 5;
            g_x2[n * 160 + tt] += g_agg[(size_t)n * 1088 + 384 + tt] + g_agg[(size_t)n * 1088 + 928 + c * 32 + e];
        }
    }
}

__global__ void reduce_part_kernel()
{
    const int T = Nn * D0;
    for (int i = blockIdx.x * blockDim.x + threadIdx.x; i < T; i += gridDim.x * blockDim.x)
        g_x0[i] += g_part[i] + g_part[T + i] + g_part[2 * T + i] + g_part[3 * T + i];
}

__global__ void gate_kernel()
{
    const int total = Nn * 544;
    for (int i = blockIdx.x * blockDim.x + threadIdx.x; i < total; i += gridDim.x * blockDim.x) {
        int n = i / 544, t = i % 544;
        if (t < 384) g_x1[n * 384 + t] *= g_gate[n * 160 + t / 3];
        else { int tt = t - 384; g_x2[n * 160 + tt] *= g_gate[n * 160 + 128 + tt / 5]; }
    }
}

__global__ void zero_kernel()
{
    const int t1 = Nn * 384, total = Nn * 384 + Nn * 160;
    for (int i = blockIdx.x * blockDim.x + threadIdx.x; i < total; i += gridDim.x * blockDim.x) {
        if (i < t1) g_x1[i] = 0.f; else g_x2[i - t1] = 0.f;
    }
}

// ------------------------- host launcher -------------------------
static inline void launch_gemm(const float* A, const float* B, float* C, const float* bias,
                               int M, int N, int K, int lda, int ldb, int ldc,
                               int act, int accum,
                               int gz = 1, int zdiv = 1,
                               size_t sA1 = 0, size_t sA2 = 0, size_t sB1 = 0, size_t sB2 = 0,
                               size_t sC1 = 0, size_t sC2 = 0)
{
    dim3 grid((N + 63) / 64, (M + 63) / 64, gz);
    gemm_f32<<<grid, 256>>>(A, B, C, bias, M, N, K, lda, ldb, ldc, act, accum, zdiv,
                            sA1, sA2, sB1, sB2, sC1, sC2);
}

extern "C" void kernel_launch(void* const* d_in, const int* in_sizes, int n_in,
                              void* d_out, int out_size)
{
    const float* x     = (const float*)d_in[0];
    const float* pos   = (const float*)d_in[1];
    const float* emb_W = (const float*)d_in[2];
    const float* emb_b = (const float*)d_in[3];
    const float* Wq    = (const float*)d_in[4];
    const float* Wk    = (const float*)d_in[5];
    const float* Wv0   = (const float*)d_in[6];
    const float* Wv1   = (const float*)d_in[7];
    const float* Wv2   = (const float*)d_in[8];
    const float* Ws1   = (const float*)d_in[9];
    const float* Ws2   = (const float*)d_in[10];
    const float* Wffa  = (const float*)d_in[11];
    const float* Wffb  = (const float*)d_in[12];
    const float* Wg    = (const float*)d_in[13];
    const float* out_W = (const float*)d_in[14];
    const float* out_b = (const float*)d_in[15];
    float* out = (float*)d_out;

    static int smem_set = 0;
    if (!smem_set) {
        cudaFuncSetAttribute(aggmix_kernel, cudaFuncAttributeMaxDynamicSharedMemorySize, AGG_SMEM);
        smem_set = 1;
    }

    void* vp;
    cudaGetSymbolAddress(&vp, g_x0);     float* px0   = (float*)vp;
    cudaGetSymbolAddress(&vp, g_inv);    float* pinv  = (float*)vp;
    cudaGetSymbolAddress(&vp, g_qk);     float* pqk   = (float*)vp;
    cudaGetSymbolAddress(&vp, g_attn);   float* pattn = (float*)vp;
    cudaGetSymbolAddress(&vp, g_V);      float* pV    = (float*)vp;
    cudaGetSymbolAddress(&vp, g_ff);     float* pff   = (float*)vp;
    cudaGetSymbolAddress(&vp, g_gate);   float* pgate = (float*)vp;
    cudaGetSymbolAddress(&vp, g_part);   float* ppart = (float*)vp;
    cudaGetSymbolAddress(&vp, g_qkpack); float* pqkp  = (float*)vp;
    cudaGetSymbolAddress(&vp, g_vpack);  float* pvp   = (float*)vp;
    cudaGetSymbolAddress(&vp, g_gpack);  float* pgp   = (float*)vp;
    cudaGetSymbolAddress(&vp, g_opack);  float* pop   = (float*)vp;

    pack_kernel<<<2048, 256>>>(Wq, Wk, Wv0, Ws1, Ws2, Wg, out_W);
    zero_kernel<<<512, 256>>>();
    // x0 = x @ emb_W + emb_b  (K=118 -> slow path)
    launch_gemm(x, emb_W, px0, emb_b, Nn, D0, 118, 118, D0, D0, 0, 0);

    for (int l = 0; l < NL; l++) {
        const float* qk_l  = pqkp + (size_t)l * 416 * 512;
        const float* vp_l  = pvp  + (size_t)l * 256 * 448;
        const float* gp_l  = pgp  + (size_t)l * 416 * 192;
        const float* Wv1_l = Wv1  + (size_t)l * D1 * D1;
        const float* Wv2_l = Wv2  + (size_t)l * D2 * D2;
        const float* Wffa_l = Wffa + (size_t)l * D0 * 512;
        const float* Wffb_l = Wffb + (size_t)l * 512 * D0;

        invariants_kernel<<<1024, 256>>>();
        // [q|k] = inv @ [Wq|Wk]
        launch_gemm(pinv, qk_l, pqk, nullptr, Nn, 512, Ff, Ff, 512, 512, 0, 0);
        // [v0|s1|s2] = x0 @ [Wv0|Ws1|Ws2]  -> g_V cols 544..959
        launch_gemm(px0, vp_l, pV + 544, nullptr, Nn, 416, D0, D0, 448, VW, 0, 0);
        v1_kernel<<<Nn, 128>>>(Wv1_l);
        v2_kernel<<<Nn, 32>>>(Wv2_l);

        attn_logits_kernel<<<dim3(32, 32, 4), 256>>>(pqk);
        softmax_kernel<<<dim3(Nn, Hh), 256>>>();
        build_w_kernel<<<4096, 256>>>(pos);

        // x0 += attn_h @ v0_h : 16 z-blocks (4 heads x 4 K-splits)
        launch_gemm(pattn, pV + 544, ppart, nullptr,
                    Nn, DHh, 512, Nn, VW, D0, 0, 0,
                    /*gz=*/16, /*zdiv=*/4,
                    /*sA1=*/NNsz, /*sA2=*/512,
                    /*sB1=*/DHh, /*sB2=*/(size_t)512 * VW,
                    /*sC1=*/DHh, /*sC2=*/(size_t)Nn * D0);
        reduce_part_kernel<<<1024, 256>>>();

        aggmix_kernel<<<dim3(17, 16), 256, AGG_SMEM>>>();
        finalize_kernel<<<1024, 256>>>();

        launch_gemm(px0, Wffa_l, pff, nullptr, Nn, 512, D0, D0, 512, 512, 1, 0);
        launch_gemm(pff, Wffb_l, px0, nullptr, Nn, D0, 512, 512, D0, D0, 0, 1);

        invariants_kernel<<<1024, 256>>>();
        launch_gemm(pinv, gp_l, pgate, nullptr, Nn, 160, Ff, Ff, 192, 160, 2, 0);
        gate_kernel<<<1024, 256>>>();
    }

    launch_gemm(px0, pop, out, out_b, Nn, NCLS, D0, D0, 64, NCLS, 0, 0);
}

// round 6
// speedup vs baseline: 5.0988x; 1.4633x over previous
#include <cuda_runtime.h>
#include <cuda_pipeline.h>
#include <math.h>
#include <stdint.h>

#define Nn 2048
#define D0 256
#define D1 128
#define D2 32
#define Ff 416
#define NCLS 10
#define NL 4
#define SQRT3 1.7320508075688772f
#define NNsz ((size_t)Nn * Nn)

typedef unsigned long long u64;

__device__ __forceinline__ u64 pack2(float x) { u64 r; asm("mov.b64 %0, {%1, %1};" : "=l"(r) : "f"(x)); return r; }
__device__ __forceinline__ void fma2(u64& d, u64 a, u64 b) { asm("fma.rn.f32x2 %0, %1, %2, %0;" : "+l"(d) : "l"(a), "l"(b)); }
__device__ __forceinline__ float2 unpack2(u64 v) { float2 f; asm("mov.b64 {%0, %1}, %2;" : "=f"(f.x), "=f"(f.y) : "l"(v)); return f; }
__device__ __forceinline__ float tf32f(float x) {
    uint32_t u; asm("cvt.rna.tf32.f32 %0, %1;" : "=r"(u) : "f"(x)); return __uint_as_float(u);
}
__device__ __forceinline__ void mma8(float c[4], const uint32_t a[4], const uint32_t b[2]) {
    asm volatile("mma.sync.aligned.m16n8k8.row.col.f32.tf32.tf32.f32 "
                 "{%0,%1,%2,%3}, {%4,%5,%6,%7}, {%8,%9}, {%0,%1,%2,%3};"
                 : "+f"(c[0]), "+f"(c[1]), "+f"(c[2]), "+f"(c[3])
                 : "r"(a[0]), "r"(a[1]), "r"(a[2]), "r"(a[3]), "r"(b[0]), "r"(b[1]));
}

// ---------------- device scratch ----------------
__device__ float g_x0[Nn * D0];
__device__ float g_x1[Nn * D1 * 3];
__device__ float g_x2[Nn * D2 * 5];
__device__ float g_inv[Nn * Ff];
__device__ float g_qk[Nn * 512];
__device__ float g_attn[(size_t)4 * Nn * Nn];
__device__ float g_a[NNsz];
__device__ float g_W[8 * NNsz];
__device__ float g_Vt[1024 * Nn];  // rows: [v1 0..383|v2 384..543|v0 544..799|s1 800..927|s2 928..959]
__device__ float g_agg[Nn * 1088];
__device__ float g_ff[Nn * 512];
__device__ float g_gate[Nn * 160];
__device__ float g_qkpack[NL * 416 * 512];
__device__ float g_vpack[NL * 256 * 448];
__device__ float g_gpack[NL * 416 * 192];
__device__ float g_opack[256 * 64];

// ---------------- pack weights ----------------
__global__ void pack_kernel(const float* __restrict__ Wq, const float* __restrict__ Wk,
                            const float* __restrict__ Wv0, const float* __restrict__ Ws1,
                            const float* __restrict__ Ws2, const float* __restrict__ Wg,
                            const float* __restrict__ outW)
{
    const int R1 = NL * 416 * 512, R2 = NL * 256 * 448, R3 = NL * 416 * 192, R4 = 256 * 64;
    const int total = R1 + R2 + R3 + R4;
    for (int i = blockIdx.x * blockDim.x + threadIdx.x; i < total; i += gridDim.x * blockDim.x) {
        if (i < R1) {
            int l = i / (416 * 512), rem = i % (416 * 512), f = rem / 512, c = rem % 512;
            g_qkpack[i] = (c < 256) ? Wq[((size_t)l * 416 + f) * 256 + c] : Wk[((size_t)l * 416 + f) * 256 + (c - 256)];
        } else if (i < R1 + R2) {
            int j = i - R1, l = j / (256 * 448), rem = j % (256 * 448), d = rem / 448, c = rem % 448;
            float v = 0.f;
            if (c < 256)      v = Wv0[((size_t)l * 256 + d) * 256 + c];
            else if (c < 384) v = Ws1[((size_t)l * 256 + d) * 128 + (c - 256)];
            else if (c < 416) v = Ws2[((size_t)l * 256 + d) * 32 + (c - 384)];
            g_vpack[j] = v;
        } else if (i < R1 + R2 + R3) {
            int j = i - R1 - R2, l = j / (416 * 192), rem = j % (416 * 192), f = rem / 192, c = rem % 192;
            g_gpack[j] = (c < 160) ? Wg[((size_t)l * 416 + f) * 160 + c] : 0.f;
        } else {
            int j = i - R1 - R2 - R3, d = j / 64, c = j % 64;
            g_opack[j] = (c < 10) ? outW[d * 10 + c] : 0.f;
        }
    }
}

// ---------------- scalar node GEMM (f32x2, cp.async) ----------------
__device__ __forceinline__ void gemm_compute32(const float (*As)[36], const float (*Bs)[72],
                                               int tx, int ty, u64 acc2[4][2])
{
#pragma unroll
    for (int k = 0; k < 32; k++) {
        u64 b0 = *(const u64*)&Bs[k][tx * 4];
        u64 b1 = *(const u64*)&Bs[k][tx * 4 + 2];
#pragma unroll
        for (int i = 0; i < 4; i++) {
            u64 a2 = pack2(As[ty * 4 + i][k]);
            fma2(acc2[i][0], a2, b0);
            fma2(acc2[i][1], a2, b1);
        }
    }
}

__global__ __launch_bounds__(256)
void gemm_f32(const float* __restrict__ A, const float* __restrict__ B,
              float* __restrict__ C, const float* __restrict__ bias,
              int M, int Ncol, int K, int lda, int ldb, int ldc,
              int act, int accum, int transC)
{
    __shared__ float As[2][64][36];
    __shared__ float Bs[2][32][72];
    int tid = threadIdx.x, tx = tid & 15, ty = tid >> 4;
    int row0 = blockIdx.y * 64, col0 = blockIdx.x * 64;
    int nc = (K + 31) >> 5;
    bool fast = ((K & 31) == 0);
    u64 acc2[4][2] = {};

    if (fast) {
#pragma unroll
        for (int t = 0; t < 2; t++) {
            int f2 = tid + t * 256, r = f2 >> 3, k4 = (f2 & 7) * 4;
            __pipeline_memcpy_async(&As[0][r][k4], &A[(size_t)(row0 + r) * lda + k4], 16);
        }
#pragma unroll
        for (int t = 0; t < 2; t++) {
            int f2 = tid + t * 256, k = f2 >> 4, c4 = (f2 & 15) * 4;
            __pipeline_memcpy_async(&Bs[0][k][c4], &B[(size_t)k * ldb + col0 + c4], 16);
        }
        __pipeline_commit();
        for (int c = 0; c < nc; c++) {
            __pipeline_wait_prior(0);
            __syncthreads();
            if (c + 1 < nc) {
                int s = (c + 1) & 1, kk = (c + 1) * 32;
#pragma unroll
                for (int t = 0; t < 2; t++) {
                    int f2 = tid + t * 256, r = f2 >> 3, k4 = (f2 & 7) * 4;
                    __pipeline_memcpy_async(&As[s][r][k4], &A[(size_t)(row0 + r) * lda + kk + k4], 16);
                }
#pragma unroll
                for (int t = 0; t < 2; t++) {
                    int f2 = tid + t * 256, k = f2 >> 4, c4 = (f2 & 15) * 4;
                    __pipeline_memcpy_async(&Bs[s][k][c4], &B[(size_t)(kk + k) * ldb + col0 + c4], 16);
                }
                __pipeline_commit();
            }
            gemm_compute32(As[c & 1], Bs[c & 1], tx, ty, acc2);
        }
    } else {
        for (int c = 0; c < nc; c++) {
            __syncthreads();
            for (int i = tid; i < 64 * 32; i += 256) {
                int r = i >> 5, k = i & 31, kg = c * 32 + k;
                As[0][r][k] = (kg < K) ? A[(size_t)(row0 + r) * lda + kg] : 0.f;
            }
            for (int i = tid; i < 32 * 64; i += 256) {
                int k = i >> 6, cc = i & 63, kg = c * 32 + k;
                float v = 0.f;
                if (kg < K && col0 + cc < Ncol) v = B[(size_t)kg * ldb + col0 + cc];
                Bs[0][k][cc] = v;
            }
            __syncthreads();
            gemm_compute32(As[0], Bs[0], tx, ty, acc2);
        }
    }
#pragma unroll
    for (int i = 0; i < 4; i++) {
        int r = row0 + ty * 4 + i;
        float2 p0 = unpack2(acc2[i][0]), p1 = unpack2(acc2[i][1]);
        float va[4] = {p0.x, p0.y, p1.x, p1.y};
#pragma unroll
        for (int j = 0; j < 4; j++) {
            int c = col0 + tx * 4 + j;
            if (c < Ncol) {
                float v = va[j];
                if (bias) v += bias[c];
                if (act == 1) v = v / (1.f + __expf(-v));
                else if (act == 2) v = 1.f / (1.f + __expf(-v));
                if (transC) C[(size_t)c * ldc + r] = tf32f(v);
                else { size_t idx = (size_t)r * ldc + c; if (accum) C[idx] += v; else C[idx] = v; }
            }
        }
    }
}

// ---------------- split-TF32 logits via mma.sync ----------------
// C[128 (query n), 128 (key m)] per CTA; 8 warps, warp tile 64x32.
#define LOG_T 34816                       // 128*68*4
#define LOG_SMEM (4 * LOG_T)
__global__ __launch_bounds__(256)
void logits_mma_kernel(const float* __restrict__ qk)
{
    extern __shared__ char dsm[];
    float (*Qhi)[68] = (float(*)[68])(dsm);
    float (*Qlo)[68] = (float(*)[68])(dsm + LOG_T);
    float (*Khi)[68] = (float(*)[68])(dsm + 2 * LOG_T);
    float (*Klo)[68] = (float(*)[68])(dsm + 3 * LOG_T);
    int tid = threadIdx.x, lane = tid & 31, wid = tid >> 5;
    int m0 = blockIdx.x * 128, n0 = blockIdx.y * 128, h = blockIdx.z;

    for (int i = tid; i < 128 * 16; i += 256) {
        int r = i >> 4, k4 = (i & 15) * 4;
        float4 v = *(const float4*)&qk[(size_t)(n0 + r) * 512 + h * 64 + k4];
        float4 hi = make_float4(tf32f(v.x), tf32f(v.y), tf32f(v.z), tf32f(v.w));
        *(float4*)&Qhi[r][k4] = hi;
        *(float4*)&Qlo[r][k4] = make_float4(tf32f(v.x - hi.x), tf32f(v.y - hi.y), tf32f(v.z - hi.z), tf32f(v.w - hi.w));
        float4 w = *(const float4*)&qk[(size_t)(m0 + r) * 512 + 256 + h * 64 + k4];
        float4 wh = make_float4(tf32f(w.x), tf32f(w.y), tf32f(w.z), tf32f(w.w));
        *(float4*)&Khi[r][k4] = wh;
        *(float4*)&Klo[r][k4] = make_float4(tf32f(w.x - wh.x), tf32f(w.y - wh.y), tf32f(w.z - wh.z), tf32f(w.w - wh.w));
    }
    __syncthreads();

    int g = lane >> 2, t = lane & 3;
    int wm = (wid >> 2) * 64, wn = (wid & 3) * 32;
    float c[4][4][4] = {};

#pragma unroll 1
    for (int k8 = 0; k8 < 64; k8 += 8) {
#pragma unroll
        for (int p = 0; p < 3; p++) {
            float (*A)[68] = (p == 2) ? Qlo : Qhi;
            float (*B)[68] = (p == 1) ? Klo : Khi;
            uint32_t a[4][4];
#pragma unroll
            for (int mt = 0; mt < 4; mt++) {
                int r = wm + mt * 16 + g;
                a[mt][0] = __float_as_uint(A[r][k8 + t]);
                a[mt][1] = __float_as_uint(A[r + 8][k8 + t]);
                a[mt][2] = __float_as_uint(A[r][k8 + t + 4]);
                a[mt][3] = __float_as_uint(A[r + 8][k8 + t + 4]);
            }
#pragma unroll
            for (int nt = 0; nt < 4; nt++) {
                int rn = wn + nt * 8 + g;
                uint32_t b[2] = {__float_as_uint(B[rn][k8 + t]), __float_as_uint(B[rn][k8 + t + 4])};
#pragma unroll
                for (int mt = 0; mt < 4; mt++) mma8(c[mt][nt], a[mt], b);
            }
        }
    }
#pragma unroll
    for (int mt = 0; mt < 4; mt++)
#pragma unroll
        for (int nt = 0; nt < 4; nt++) {
            int row = n0 + wm + mt * 16 + g, col = m0 + wn + nt * 8 + 2 * t;
            size_t base = ((size_t)h * Nn + row) * Nn + col;
            *(float2*)&g_attn[base] = make_float2(c[mt][nt][0] * 0.125f, c[mt][nt][1] * 0.125f);
            *(float2*)&g_attn[base + 8 * (size_t)Nn] = make_float2(c[mt][nt][2] * 0.125f, c[mt][nt][3] * 0.125f);
        }
}

// ---------------- TF32 combined agg/mix/agg0 via mma.sync ----------------
// C[128 rows, NC cols] = A(128 x 2048) @ Vt_rows^T. 4 warps, warp tile 64 x NC/2.
template<int NC>
__global__ __launch_bounds__(128)
void nn_mma_kernel()
{
    extern __shared__ char dsm[];
    constexpr int ASZ = 128 * 36 * 4;
    constexpr int BSZ = NC * 36 * 4;
    constexpr int STG = ASZ + BSZ;
    constexpr int NT = NC / 16;   // n-tiles per warp
    int tid = threadIdx.x, lane = tid & 31, wid = tid >> 5;
    int ct = blockIdx.x, n0 = blockIdx.y * 128;

    const float* Ap; float* Cp; int vtrow, col0, ldc, acc;
    if (NC == 64) {
        if (ct < 8)       { Ap = g_a; vtrow = ct * 64; col0 = ct * 64; Cp = g_agg; ldc = 1088; acc = 0; }
        else if (ct < 14) { int q = ct - 8, cc = q >> 1, half = q & 1;
                            Ap = g_W + (size_t)cc * NNsz; vtrow = 800 + half * 64;
                            col0 = 544 + cc * 128 + half * 64; Cp = g_agg; ldc = 1088; acc = 0; }
        else              { int h = ct - 14; Ap = g_attn + (size_t)h * NNsz;
                            vtrow = 544 + h * 64; col0 = h * 64; Cp = g_x0; ldc = 256; acc = 1; }
    } else {
        if (ct == 0) { Ap = g_a; vtrow = 512; col0 = 512; }
        else         { int cc = ct - 1; Ap = g_W + (size_t)(3 + cc) * NNsz; vtrow = 928 + cc * 32; col0 = 928 + cc * 32; }
        Cp = g_agg; ldc = 1088; acc = 0;
    }
    const float* Arow = Ap + (size_t)n0 * Nn;
    const float* Brow = g_Vt + (size_t)vtrow * Nn;

    int g = lane >> 2, t = lane & 3;
    int wm = (wid >> 1) * 64, wn = (wid & 1) * (NC / 2);
    float c[4][NT][4] = {};

    const int NCH = Nn / 32;
    // prologue: chunk 0 -> stage 0
    {
        float (*As)[36] = (float(*)[36])(dsm);
        float (*Bs)[36] = (float(*)[36])(dsm + ASZ);
#pragma unroll
        for (int i = 0; i < 8; i++) {
            int idx = tid + i * 128, r = idx >> 3, k4 = (idx & 7) * 4;
            __pipeline_memcpy_async(&As[r][k4], &Arow[(size_t)r * Nn + k4], 16);
        }
#pragma unroll
        for (int i = 0; i < NC / 16; i++) {
            int idx = tid + i * 128, r = idx >> 3, k4 = (idx & 7) * 4;
            __pipeline_memcpy_async(&Bs[r][k4], &Brow[(size_t)r * Nn + k4], 16);
        }
        __pipeline_commit();
    }
#pragma unroll 1
    for (int ch = 0; ch < NCH; ch++) {
        __pipeline_wait_prior(0);
        __syncthreads();
        if (ch + 1 < NCH) {
            int s = (ch + 1) & 1, kk = (ch + 1) * 32;
            float (*As)[36] = (float(*)[36])(dsm + s * STG);
            float (*Bs)[36] = (float(*)[36])(dsm + s * STG + ASZ);
#pragma unroll
            for (int i = 0; i < 8; i++) {
                int idx = tid + i * 128, r = idx >> 3, k4 = (idx & 7) * 4;
                __pipeline_memcpy_async(&As[r][k4], &Arow[(size_t)r * Nn + kk + k4], 16);
            }
#pragma unroll
            for (int i = 0; i < NC / 16; i++) {
                int idx = tid + i * 128, r = idx >> 3, k4 = (idx & 7) * 4;
                __pipeline_memcpy_async(&Bs[r][k4], &Brow[(size_t)r * Nn + kk + k4], 16);
            }
            __pipeline_commit();
        }
        float (*As)[36] = (float(*)[36])(dsm + (ch & 1) * STG);
        float (*Bs)[36] = (float(*)[36])(dsm + (ch & 1) * STG + ASZ);
#pragma unroll
        for (int k8 = 0; k8 < 32; k8 += 8) {
            uint32_t a[4][4];
#pragma unroll
            for (int mt = 0; mt < 4; mt++) {
                int r = wm + mt * 16 + g;
                a[mt][0] = __float_as_uint(As[r][k8 + t]);
                a[mt][1] = __float_as_uint(As[r + 8][k8 + t]);
                a[mt][2] = __float_as_uint(As[r][k8 + t + 4]);
                a[mt][3] = __float_as_uint(As[r + 8][k8 + t + 4]);
            }
#pragma unroll
            for (int nt = 0; nt < NT; nt++) {
                int rn = wn + nt * 8 + g;
                uint32_t b[2] = {__float_as_uint(Bs[rn][k8 + t]), __float_as_uint(Bs[rn][k8 + t + 4])};
#pragma unroll
                for (int mt = 0; mt < 4; mt++) mma8(c[mt][nt], a[mt], b);
            }
        }
    }
#pragma unroll
    for (int mt = 0; mt < 4; mt++)
#pragma unroll
        for (int nt = 0; nt < NT; nt++) {
            int row = n0 + wm + mt * 16 + g, col = col0 + wn + nt * 8 + 2 * t;
            size_t i0 = (size_t)row * ldc + col, i1 = (size_t)(row + 8) * ldc + col;
            if (acc) {
                float2 o0 = *(float2*)&Cp[i0], o1 = *(float2*)&Cp[i1];
                *(float2*)&Cp[i0] = make_float2(o0.x + c[mt][nt][0], o0.y + c[mt][nt][1]);
                *(float2*)&Cp[i1] = make_float2(o1.x + c[mt][nt][2], o1.y + c[mt][nt][3]);
            } else {
                *(float2*)&Cp[i0] = make_float2(c[mt][nt][0], c[mt][nt][1]);
                *(float2*)&Cp[i1] = make_float2(c[mt][nt][2], c[mt][nt][3]);
            }
        }
}

// ---------------- softmax (tf32-rounded output) ----------------
__global__ __launch_bounds__(256)
void softmax_kernel()
{
    int n = blockIdx.x, h = blockIdx.y;
    float* p = g_attn + ((size_t)h * Nn + n) * Nn;
    __shared__ float row[Nn];
    __shared__ float red[256];
    int tid = threadIdx.x;
    float mx = -1e30f;
    for (int i = tid * 4; i < Nn; i += 1024) {
        float4 v = *(const float4*)&p[i];
        *(float4*)&row[i] = v;
        mx = fmaxf(mx, fmaxf(fmaxf(v.x, v.y), fmaxf(v.z, v.w)));
    }
    red[tid] = mx; __syncthreads();
    for (int s = 128; s > 0; s >>= 1) { if (tid < s) red[tid] = fmaxf(red[tid], red[tid + s]); __syncthreads(); }
    float m = red[0]; __syncthreads();
    float sum = 0.f;
    for (int i = tid; i < Nn; i += 256) { float e = __expf(row[i] - m); row[i] = e; sum += e; }
    red[tid] = sum; __syncthreads();
    for (int s = 128; s > 0; s >>= 1) { if (tid < s) red[tid] += red[tid + s]; __syncthreads(); }
    float inv = 1.f / red[0]; __syncthreads();
    for (int i = tid * 4; i < Nn; i += 1024) {
        float4 v = *(float4*)&row[i];
        *(float4*)&p[i] = make_float4(tf32f(v.x * inv), tf32f(v.y * inv), tf32f(v.z * inv), tf32f(v.w * inv));
    }
}

// ---------------- build class weight matrices (tf32-rounded) ----------------
__global__ void build_w_kernel(const float* __restrict__ pos)
{
    for (size_t q = (size_t)blockIdx.x * blockDim.x + threadIdx.x; q < NNsz / 4;
         q += (size_t)gridDim.x * blockDim.x) {
        size_t i4 = q * 4;
        int n = (int)(i4 >> 11), m = (int)(i4 & 2047);
        float4 h0 = *(const float4*)&g_attn[i4];
        float4 h1 = *(const float4*)&g_attn[NNsz + i4];
        float4 h2 = *(const float4*)&g_attn[2 * NNsz + i4];
        float4 h3 = *(const float4*)&g_attn[3 * NNsz + i4];
        float av[4] = {0.25f * (h0.x + h1.x + h2.x + h3.x), 0.25f * (h0.y + h1.y + h2.y + h3.y),
                       0.25f * (h0.z + h1.z + h2.z + h3.z), 0.25f * (h0.w + h1.w + h2.w + h3.w)};
        float pnx = pos[n * 3 + 0], pny = pos[n * 3 + 1], pnz = pos[n * 3 + 2];
        float o[9][4];
#pragma unroll
        for (int tt = 0; tt < 4; tt++) {
            float a = av[tt];
            float rx = pos[(m + tt) * 3 + 0] - pnx;
            float ry = pos[(m + tt) * 3 + 1] - pny;
            float rz = pos[(m + tt) * 3 + 2] - pnz;
            float r2 = rx * rx + ry * ry + rz * rz;
            bool ok = r2 > 1e-12f;
            float inv = ok ? rsqrtf(r2) : 0.f;
            float valid = ok ? 1.f : 0.f;
            float ux = rx * inv, uy = ry * inv, uz = rz * inv;
            o[0][tt] = tf32f(a);
            o[1][tt] = tf32f(a * ux); o[2][tt] = tf32f(a * uy); o[3][tt] = tf32f(a * uz);
            o[4][tt] = tf32f(a * (SQRT3 * ux * uy));
            o[5][tt] = tf32f(a * (SQRT3 * uy * uz));
            o[6][tt] = tf32f(a * (0.5f * (3.f * uz * uz - 1.f)) * valid);
            o[7][tt] = tf32f(a * (SQRT3 * ux * uz));
            o[8][tt] = tf32f(a * (0.5f * SQRT3 * (ux * ux - uy * uy)));
        }
        *(float4*)&g_a[i4] = make_float4(o[0][0], o[0][1], o[0][2], o[0][3]);
#pragma unroll
        for (int cc = 0; cc < 8; cc++)
            *(float4*)&g_W[cc * NNsz + i4] = make_float4(o[cc + 1][0], o[cc + 1][1], o[cc + 1][2], o[cc + 1][3]);
    }
}

// ---------------- invariants ----------------
__global__ void invariants_kernel()
{
    const int total = Nn * Ff;
    for (int i = blockIdx.x * blockDim.x + threadIdx.x; i < total; i += gridDim.x * blockDim.x) {
        int n = i / Ff, c = i % Ff;
        float v;
        if (c < D0) v = g_x0[n * D0 + c];
        else if (c < D0 + D1) {
            const float* p = &g_x1[(n * D1 + (c - D0)) * 3];
            v = sqrtf(p[0] * p[0] + p[1] * p[1] + p[2] * p[2]);
        } else {
            const float* p = &g_x2[(n * D2 + (c - D0 - D1)) * 5];
            v = sqrtf(p[0] * p[0] + p[1] * p[1] + p[2] * p[2] + p[3] * p[3] + p[4] * p[4]);
        }
        g_inv[i] = v;
    }
}

// ---------------- v1/v2 channel mixes (transposed tf32 writes) ----------------
__global__ __launch_bounds__(128)
void v1_kernel(const float* __restrict__ Wv1)
{
    int m = blockIdx.x;
    __shared__ float sx[D1 * 3];
    int tid = threadIdx.x;
    for (int i = tid; i < D1 * 3; i += 128) sx[i] = g_x1[m * D1 * 3 + i];
    __syncthreads();
    float a0 = 0.f, a1 = 0.f, a2 = 0.f;
#pragma unroll 8
    for (int d = 0; d < D1; d++) {
        float w = Wv1[d * D1 + tid];
        a0 += sx[d * 3 + 0] * w;
        a1 += sx[d * 3 + 1] * w;
        a2 += sx[d * 3 + 2] * w;
    }
    g_Vt[(size_t)(tid * 3 + 0) * Nn + m] = tf32f(a0);
    g_Vt[(size_t)(tid * 3 + 1) * Nn + m] = tf32f(a1);
    g_Vt[(size_t)(tid * 3 + 2) * Nn + m] = tf32f(a2);
}

__global__ __launch_bounds__(32)
void v2_kernel(const float* __restrict__ Wv2)
{
    int m = blockIdx.x;
    __shared__ float sx[D2 * 5];
    int tid = threadIdx.x;
    for (int i = tid; i < D2 * 5; i += 32) sx[i] = g_x2[m * D2 * 5 + i];
    __syncthreads();
    float a[5] = {};
#pragma unroll 8
    for (int d = 0; d < D2; d++) {
        float w = Wv2[d * D2 + tid];
#pragma unroll
        for (int c = 0; c < 5; c++) a[c] += sx[d * 5 + c] * w;
    }
#pragma unroll
    for (int c = 0; c < 5; c++) g_Vt[(size_t)(384 + tid * 5 + c) * Nn + m] = tf32f(a[c]);
}

// ---------------- finalize / gate / zero ----------------
__global__ void finalize_kernel()
{
    const int total = Nn * 544;
    for (int i = blockIdx.x * blockDim.x + threadIdx.x; i < total; i += gridDim.x * blockDim.x) {
        int n = i / 544, t = i % 544;
        if (t < 384) {
            int d = t / 3, c = t % 3;
            g_x1[n * 384 + t] += g_agg[(size_t)n * 1088 + t] + g_agg[(size_t)n * 1088 + 544 + c * 128 + d];
        } else {
            int tt = t - 384, e = tt / 5, c = tt % 5;
            g_x2[n * 160 + tt] += g_agg[(size_t)n * 1088 + 384 + tt] + g_agg[(size_t)n * 1088 + 928 + c * 32 + e];
        }
    }
}

__global__ void gate_kernel()
{
    const int total = Nn * 544;
    for (int i = blockIdx.x * blockDim.x + threadIdx.x; i < total; i += gridDim.x * blockDim.x) {
        int n = i / 544, t = i % 544;
        if (t < 384) g_x1[n * 384 + t] *= g_gate[n * 160 + t / 3];
        else { int tt = t - 384; g_x2[n * 160 + tt] *= g_gate[n * 160 + 128 + tt / 5]; }
    }
}

__global__ void zero_kernel()
{
    const int t1 = Nn * 384, total = Nn * 384 + Nn * 160;
    for (int i = blockIdx.x * blockDim.x + threadIdx.x; i < total; i += gridDim.x * blockDim.x) {
        if (i < t1) g_x1[i] = 0.f; else g_x2[i - t1] = 0.f;
    }
}

// ---------------- host ----------------
static inline void launch_gemm(const float* A, const float* B, float* C, const float* bias,
                               int M, int N, int K, int lda, int ldb, int ldc,
                               int act, int accum, int transC = 0)
{
    dim3 grid((N + 63) / 64, (M + 63) / 64);
    gemm_f32<<<grid, 256>>>(A, B, C, bias, M, N, K, lda, ldb, ldc, act, accum, transC);
}

#define NN64_SMEM (2 * (128 * 36 * 4 + 64 * 36 * 4))
#define NN32_SMEM (2 * (128 * 36 * 4 + 32 * 36 * 4))

extern "C" void kernel_launch(void* const* d_in, const int* in_sizes, int n_in,
                              void* d_out, int out_size)
{
    const float* x     = (const float*)d_in[0];
    const float* pos   = (const float*)d_in[1];
    const float* emb_W = (const float*)d_in[2];
    const float* emb_b = (const float*)d_in[3];
    const float* Wq    = (const float*)d_in[4];
    const float* Wk    = (const float*)d_in[5];
    const float* Wv0   = (const float*)d_in[6];
    const float* Wv1   = (const float*)d_in[7];
    const float* Wv2   = (const float*)d_in[8];
    const float* Ws1   = (const float*)d_in[9];
    const float* Ws2   = (const float*)d_in[10];
    const float* Wffa  = (const float*)d_in[11];
    const float* Wffb  = (const float*)d_in[12];
    const float* Wg    = (const float*)d_in[13];
    const float* out_W = (const float*)d_in[14];
    const float* out_b = (const float*)d_in[15];
    float* out = (float*)d_out;

    static int once = 0;
    if (!once) {
        cudaFuncSetAttribute(logits_mma_kernel, cudaFuncAttributeMaxDynamicSharedMemorySize, LOG_SMEM);
        cudaFuncSetAttribute(nn_mma_kernel<64>, cudaFuncAttributeMaxDynamicSharedMemorySize, NN64_SMEM);
        cudaFuncSetAttribute(nn_mma_kernel<32>, cudaFuncAttributeMaxDynamicSharedMemorySize, NN32_SMEM);
        once = 1;
    }

    void* vp;
    cudaGetSymbolAddress(&vp, g_x0);     float* px0   = (float*)vp;
    cudaGetSymbolAddress(&vp, g_inv);    float* pinv  = (float*)vp;
    cudaGetSymbolAddress(&vp, g_qk);     float* pqk   = (float*)vp;
    cudaGetSymbolAddress(&vp, g_Vt);     float* pVt   = (float*)vp;
    cudaGetSymbolAddress(&vp, g_ff);     float* pff   = (float*)vp;
    cudaGetSymbolAddress(&vp, g_gate);   float* pgate = (float*)vp;
    cudaGetSymbolAddress(&vp, g_qkpack); float* pqkp  = (float*)vp;
    cudaGetSymbolAddress(&vp, g_vpack);  float* pvp   = (float*)vp;
    cudaGetSymbolAddress(&vp, g_gpack);  float* pgp   = (float*)vp;
    cudaGetSymbolAddress(&vp, g_opack);  float* pop   = (float*)vp;

    pack_kernel<<<2048, 256>>>(Wq, Wk, Wv0, Ws1, Ws2, Wg, out_W);
    zero_kernel<<<512, 256>>>();
    launch_gemm(x, emb_W, px0, emb_b, Nn, D0, 118, 118, D0, D0, 0, 0);

    for (int l = 0; l < NL; l++) {
        const float* qk_l   = pqkp + (size_t)l * 416 * 512;
        const float* vp_l   = pvp  + (size_t)l * 256 * 448;
        const float* gp_l   = pgp  + (size_t)l * 416 * 192;
        const float* Wv1_l  = Wv1  + (size_t)l * D1 * D1;
        const float* Wv2_l  = Wv2  + (size_t)l * D2 * D2;
        const float* Wffa_l = Wffa + (size_t)l * D0 * 512;
        const float* Wffb_l = Wffb + (size_t)l * 512 * D0;

        invariants_kernel<<<1024, 256>>>();
        launch_gemm(pinv, qk_l, pqk, nullptr, Nn, 512, Ff, Ff, 512, 512, 0, 0);
        // [v0|s1|s2] -> transposed tf32 rows 544..959 of g_Vt
        launch_gemm(px0, vp_l, pVt + (size_t)544 * Nn, nullptr, Nn, 416, D0, D0, 448, Nn, 0, 0, 1);
        v1_kernel<<<Nn, 128>>>(Wv1_l);
        v2_kernel<<<Nn, 32>>>(Wv2_l);

        logits_mma_kernel<<<dim3(16, 16, 4), 256, LOG_SMEM>>>(pqk);
        softmax_kernel<<<dim3(Nn, 4), 256>>>();
        build_w_kernel<<<4096, 256>>>(pos);

        nn_mma_kernel<64><<<dim3(18, 16), 128, NN64_SMEM>>>();
        nn_mma_kernel<32><<<dim3(6, 16), 128, NN32_SMEM>>>();
        finalize_kernel<<<1024, 256>>>();

        launch_gemm(px0, Wffa_l, pff, nullptr, Nn, 512, D0, D0, 512, 512, 1, 0);
        launch_gemm(pff, Wffb_l, px0, nullptr, Nn, D0, 512, 512, D0, D0, 0, 1);

        invariants_kernel<<<1024, 256>>>();
        launch_gemm(pinv, gp_l, pgate, nullptr, Nn, 160, Ff, Ff, 192, 160, 2, 0);
        gate_kernel<<<1024, 256>>>();
    }
    launch_gemm(px0, pop, out, out_b, Nn, NCLS, D0, D0, 64, NCLS, 0, 0);
}

// round 7
// speedup vs baseline: 5.4653x; 1.0719x over previous
#include <cuda_runtime.h>
#include <cuda_pipeline.h>
#include <cuda_bf16.h>
#include <math.h>
#include <stdint.h>

#define Nn 2048
#define D0 256
#define D1 128
#define D2 32
#define Ff 416
#define NCLS 10
#define NL 4
#define SQRT3 1.7320508075688772f
#define NNsz ((size_t)Nn * Nn)

typedef unsigned long long u64;

__device__ __forceinline__ u64 pack2(float x) { u64 r; asm("mov.b64 %0, {%1, %1};" : "=l"(r) : "f"(x)); return r; }
__device__ __forceinline__ void fma2(u64& d, u64 a, u64 b) { asm("fma.rn.f32x2 %0, %1, %2, %0;" : "+l"(d) : "l"(a), "l"(b)); }
__device__ __forceinline__ float2 unpack2(u64 v) { float2 f; asm("mov.b64 {%0, %1}, %2;" : "=f"(f.x), "=f"(f.y) : "l"(v)); return f; }
__device__ __forceinline__ float tf32f(float x) {
    uint32_t u; asm("cvt.rna.tf32.f32 %0, %1;" : "=r"(u) : "f"(x)); return __uint_as_float(u);
}
__device__ __forceinline__ unsigned short bfu(float x) {
    __nv_bfloat16 b = __float2bfloat16_rn(x); return *(unsigned short*)&b;
}
__device__ __forceinline__ float bff(unsigned short u) {
    __nv_bfloat16 b = *(__nv_bfloat16*)&u; return __bfloat162float(b);
}
__device__ __forceinline__ void mma8(float c[4], const uint32_t a[4], const uint32_t b[2]) {
    asm volatile("mma.sync.aligned.m16n8k8.row.col.f32.tf32.tf32.f32 "
                 "{%0,%1,%2,%3}, {%4,%5,%6,%7}, {%8,%9}, {%0,%1,%2,%3};"
                 : "+f"(c[0]), "+f"(c[1]), "+f"(c[2]), "+f"(c[3])
                 : "r"(a[0]), "r"(a[1]), "r"(a[2]), "r"(a[3]), "r"(b[0]), "r"(b[1]));
}
__device__ __forceinline__ void mma16(float c[4], const uint32_t a[4], const uint32_t b[2]) {
    asm volatile("mma.sync.aligned.m16n8k16.row.col.f32.bf16.bf16.f32 "
                 "{%0,%1,%2,%3}, {%4,%5,%6,%7}, {%8,%9}, {%0,%1,%2,%3};"
                 : "+f"(c[0]), "+f"(c[1]), "+f"(c[2]), "+f"(c[3])
                 : "r"(a[0]), "r"(a[1]), "r"(a[2]), "r"(a[3]), "r"(b[0]), "r"(b[1]));
}

// ---------------- device scratch ----------------
__device__ float g_x0[Nn * D0];
__device__ float g_x1[Nn * D1 * 3];
__device__ float g_x2[Nn * D2 * 5];
__device__ float g_inv[Nn * Ff];
__device__ float g_qk[Nn * 512];
__device__ float g_attn[(size_t)4 * Nn * Nn];
__device__ float g_a[NNsz];
__device__ float g_W[8 * NNsz];
__device__ float g_Vt[1024 * Nn];  // rows: [v1 0..383|v2 384..543|v0 544..799|s1 800..927|s2 928..959]
__device__ float g_agg[Nn * 1088];
__device__ float g_ff[Nn * 512];
__device__ float g_gate[Nn * 160];
__device__ float g_qkpack[NL * 416 * 512];
__device__ float g_vpack[NL * 256 * 448];
__device__ float g_gpack[NL * 416 * 192];
__device__ float g_opack[256 * 64];

// ---------------- pack weights ----------------
__global__ void pack_kernel(const float* __restrict__ Wq, const float* __restrict__ Wk,
                            const float* __restrict__ Wv0, const float* __restrict__ Ws1,
                            const float* __restrict__ Ws2, const float* __restrict__ Wg,
                            const float* __restrict__ outW)
{
    const int R1 = NL * 416 * 512, R2 = NL * 256 * 448, R3 = NL * 416 * 192, R4 = 256 * 64;
    const int total = R1 + R2 + R3 + R4;
    for (int i = blockIdx.x * blockDim.x + threadIdx.x; i < total; i += gridDim.x * blockDim.x) {
        if (i < R1) {
            int l = i / (416 * 512), rem = i % (416 * 512), f = rem / 512, c = rem % 512;
            g_qkpack[i] = (c < 256) ? Wq[((size_t)l * 416 + f) * 256 + c] : Wk[((size_t)l * 416 + f) * 256 + (c - 256)];
        } else if (i < R1 + R2) {
            int j = i - R1, l = j / (256 * 448), rem = j % (256 * 448), d = rem / 448, c = rem % 448;
            float v = 0.f;
            if (c < 256)      v = Wv0[((size_t)l * 256 + d) * 256 + c];
            else if (c < 384) v = Ws1[((size_t)l * 256 + d) * 128 + (c - 256)];
            else if (c < 416) v = Ws2[((size_t)l * 256 + d) * 32 + (c - 384)];
            g_vpack[j] = v;
        } else if (i < R1 + R2 + R3) {
            int j = i - R1 - R2, l = j / (416 * 192), rem = j % (416 * 192), f = rem / 192, c = rem % 192;
            g_gpack[j] = (c < 160) ? Wg[((size_t)l * 416 + f) * 160 + c] : 0.f;
        } else {
            int j = i - R1 - R2 - R3, d = j / 64, c = j % 64;
            g_opack[j] = (c < 10) ? outW[d * 10 + c] : 0.f;
        }
    }
}

// ---------------- scalar node GEMM (f32x2, cp.async) ----------------
__device__ __forceinline__ void gemm_compute32(const float (*As)[36], const float (*Bs)[72],
                                               int tx, int ty, u64 acc2[4][2])
{
#pragma unroll
    for (int k = 0; k < 32; k++) {
        u64 b0 = *(const u64*)&Bs[k][tx * 4];
        u64 b1 = *(const u64*)&Bs[k][tx * 4 + 2];
#pragma unroll
        for (int i = 0; i < 4; i++) {
            u64 a2 = pack2(As[ty * 4 + i][k]);
            fma2(acc2[i][0], a2, b0);
            fma2(acc2[i][1], a2, b1);
        }
    }
}

__global__ __launch_bounds__(256)
void gemm_f32(const float* __restrict__ A, const float* __restrict__ B,
              float* __restrict__ C, const float* __restrict__ bias,
              int M, int Ncol, int K, int lda, int ldb, int ldc,
              int act, int accum, int transC)
{
    __shared__ float As[2][64][36];
    __shared__ float Bs[2][32][72];
    int tid = threadIdx.x, tx = tid & 15, ty = tid >> 4;
    int row0 = blockIdx.y * 64, col0 = blockIdx.x * 64;
    int nc = (K + 31) >> 5;
    bool fast = ((K & 31) == 0);
    u64 acc2[4][2] = {};

    if (fast) {
#pragma unroll
        for (int t = 0; t < 2; t++) {
            int f2 = tid + t * 256, r = f2 >> 3, k4 = (f2 & 7) * 4;
            __pipeline_memcpy_async(&As[0][r][k4], &A[(size_t)(row0 + r) * lda + k4], 16);
        }
#pragma unroll
        for (int t = 0; t < 2; t++) {
            int f2 = tid + t * 256, k = f2 >> 4, c4 = (f2 & 15) * 4;
            __pipeline_memcpy_async(&Bs[0][k][c4], &B[(size_t)k * ldb + col0 + c4], 16);
        }
        __pipeline_commit();
        for (int c = 0; c < nc; c++) {
            __pipeline_wait_prior(0);
            __syncthreads();
            if (c + 1 < nc) {
                int s = (c + 1) & 1, kk = (c + 1) * 32;
#pragma unroll
                for (int t = 0; t < 2; t++) {
                    int f2 = tid + t * 256, r = f2 >> 3, k4 = (f2 & 7) * 4;
                    __pipeline_memcpy_async(&As[s][r][k4], &A[(size_t)(row0 + r) * lda + kk + k4], 16);
                }
#pragma unroll
                for (int t = 0; t < 2; t++) {
                    int f2 = tid + t * 256, k = f2 >> 4, c4 = (f2 & 15) * 4;
                    __pipeline_memcpy_async(&Bs[s][k][c4], &B[(size_t)(kk + k) * ldb + col0 + c4], 16);
                }
                __pipeline_commit();
            }
            gemm_compute32(As[c & 1], Bs[c & 1], tx, ty, acc2);
        }
    } else {
        for (int c = 0; c < nc; c++) {
            __syncthreads();
            for (int i = tid; i < 64 * 32; i += 256) {
                int r = i >> 5, k = i & 31, kg = c * 32 + k;
                As[0][r][k] = (kg < K) ? A[(size_t)(row0 + r) * lda + kg] : 0.f;
            }
            for (int i = tid; i < 32 * 64; i += 256) {
                int k = i >> 6, cc = i & 63, kg = c * 32 + k;
                float v = 0.f;
                if (kg < K && col0 + cc < Ncol) v = B[(size_t)kg * ldb + col0 + cc];
                Bs[0][k][cc] = v;
            }
            __syncthreads();
            gemm_compute32(As[0], Bs[0], tx, ty, acc2);
        }
    }
#pragma unroll
    for (int i = 0; i < 4; i++) {
        int r = row0 + ty * 4 + i;
        float2 p0 = unpack2(acc2[i][0]), p1 = unpack2(acc2[i][1]);
        float va[4] = {p0.x, p0.y, p1.x, p1.y};
#pragma unroll
        for (int j = 0; j < 4; j++) {
            int c = col0 + tx * 4 + j;
            if (c < Ncol) {
                float v = va[j];
                if (bias) v += bias[c];
                if (act == 1) v = v / (1.f + __expf(-v));
                else if (act == 2) v = 1.f / (1.f + __expf(-v));
                if (transC) C[(size_t)c * ldc + r] = tf32f(v);
                else { size_t idx = (size_t)r * ldc + c; if (accum) C[idx] += v; else C[idx] = v; }
            }
        }
    }
}

// ---------------- split-bf16 logits via mma.sync m16n8k16 ----------------
// C[128 n, 128 m] per CTA; 8 warps, warp tile 64x32. 3 passes: hh, h*lo, lo*h.
#define LOG_LD 72
#define LOG_T (128 * LOG_LD * 2)     // 18432 bytes per array
#define LOG_SMEM (4 * LOG_T)         // 73728
__global__ __launch_bounds__(256)
void logits_mma_kernel(const float* __restrict__ qk)
{
    extern __shared__ char dsm[];
    unsigned short (*Qhi)[LOG_LD] = (unsigned short(*)[LOG_LD])(dsm);
    unsigned short (*Qlo)[LOG_LD] = (unsigned short(*)[LOG_LD])(dsm + LOG_T);
    unsigned short (*Khi)[LOG_LD] = (unsigned short(*)[LOG_LD])(dsm + 2 * LOG_T);
    unsigned short (*Klo)[LOG_LD] = (unsigned short(*)[LOG_LD])(dsm + 3 * LOG_T);
    int tid = threadIdx.x, lane = tid & 31, wid = tid >> 5;
    int m0 = blockIdx.x * 128, n0 = blockIdx.y * 128, h = blockIdx.z;

    for (int i = tid; i < 128 * 16; i += 256) {
        int r = i >> 4, k4 = (i & 15) * 4;
        float4 v = *(const float4*)&qk[(size_t)(n0 + r) * 512 + h * 64 + k4];
        ushort4 hs, ls;
        hs.x = bfu(v.x); ls.x = bfu(v.x - bff(hs.x));
        hs.y = bfu(v.y); ls.y = bfu(v.y - bff(hs.y));
        hs.z = bfu(v.z); ls.z = bfu(v.z - bff(hs.z));
        hs.w = bfu(v.w); ls.w = bfu(v.w - bff(hs.w));
        *(ushort4*)&Qhi[r][k4] = hs;
        *(ushort4*)&Qlo[r][k4] = ls;
        float4 w = *(const float4*)&qk[(size_t)(m0 + r) * 512 + 256 + h * 64 + k4];
        hs.x = bfu(w.x); ls.x = bfu(w.x - bff(hs.x));
        hs.y = bfu(w.y); ls.y = bfu(w.y - bff(hs.y));
        hs.z = bfu(w.z); ls.z = bfu(w.z - bff(hs.z));
        hs.w = bfu(w.w); ls.w = bfu(w.w - bff(hs.w));
        *(ushort4*)&Khi[r][k4] = hs;
        *(ushort4*)&Klo[r][k4] = ls;
    }
    __syncthreads();

    int g = lane >> 2, t = lane & 3;
    int wm = (wid >> 2) * 64, wn = (wid & 3) * 32;
    float c[4][4][4] = {};

#pragma unroll
    for (int k0 = 0; k0 < 64; k0 += 16) {
#pragma unroll
        for (int p = 0; p < 3; p++) {
            unsigned short (*A)[LOG_LD] = (p == 2) ? Qlo : Qhi;
            unsigned short (*B)[LOG_LD] = (p == 1) ? Klo : Khi;
            uint32_t a[4][4];
#pragma unroll
            for (int mt = 0; mt < 4; mt++) {
                int r = wm + mt * 16 + g;
                a[mt][0] = *(const uint32_t*)&A[r][k0 + 2 * t];
                a[mt][1] = *(const uint32_t*)&A[r + 8][k0 + 2 * t];
                a[mt][2] = *(const uint32_t*)&A[r][k0 + 2 * t + 8];
                a[mt][3] = *(const uint32_t*)&A[r + 8][k0 + 2 * t + 8];
            }
#pragma unroll
            for (int nt = 0; nt < 4; nt++) {
                int rn = wn + nt * 8 + g;
                uint32_t b[2] = {*(const uint32_t*)&B[rn][k0 + 2 * t],
                                 *(const uint32_t*)&B[rn][k0 + 2 * t + 8]};
#pragma unroll
                for (int mt = 0; mt < 4; mt++) mma16(c[mt][nt], a[mt], b);
            }
        }
    }
#pragma unroll
    for (int mt = 0; mt < 4; mt++)
#pragma unroll
        for (int nt = 0; nt < 4; nt++) {
            int row = n0 + wm + mt * 16 + g, col = m0 + wn + nt * 8 + 2 * t;
            size_t base = ((size_t)h * Nn + row) * Nn + col;
            *(float2*)&g_attn[base] = make_float2(c[mt][nt][0] * 0.125f, c[mt][nt][1] * 0.125f);
            *(float2*)&g_attn[base + 8 * (size_t)Nn] = make_float2(c[mt][nt][2] * 0.125f, c[mt][nt][3] * 0.125f);
        }
}

// ---------------- TF32 combined agg/mix/agg0 via mma.sync (single launch) ----------------
// 17 configs x 16 row-blocks. 256 threads, warp tile 64 x (NC/4). K=2048, chunk 32, 2-stage cp.async.
#define NN_ASZ (128 * 36 * 4)
#define NN_BSZ (128 * 36 * 4)
#define NN_STG (NN_ASZ + NN_BSZ)
#define NN_SMEM (2 * NN_STG)
__global__ __launch_bounds__(256)
void nn_mma_kernel()
{
    extern __shared__ char dsm[];
    int tid = threadIdx.x, lane = tid & 31, wid = tid >> 5;
    int ct = blockIdx.x, n0 = blockIdx.y * 128;

    const float* Ap; float* Cp; int NC, vtrow, col0, ldc, acc;
    if (ct < 4)       { NC = 128; Ap = g_a; vtrow = ct * 128; col0 = ct * 128; Cp = g_agg; ldc = 1088; acc = 0; }
    else if (ct < 7)  { NC = 128; int c = ct - 4; Ap = g_W + (size_t)c * NNsz; vtrow = 800; col0 = 544 + c * 128; Cp = g_agg; ldc = 1088; acc = 0; }
    else if (ct == 7) { NC = 32;  Ap = g_a; vtrow = 512; col0 = 512; Cp = g_agg; ldc = 1088; acc = 0; }
    else if (ct < 13) { NC = 32;  int c = ct - 8; Ap = g_W + (size_t)(3 + c) * NNsz; vtrow = 928; col0 = 928 + c * 32; Cp = g_agg; ldc = 1088; acc = 0; }
    else              { NC = 64;  int h = ct - 13; Ap = g_attn + (size_t)h * NNsz; vtrow = 544 + h * 64; col0 = h * 64; Cp = g_x0; ldc = 256; acc = 1; }

    const float* Arow = Ap + (size_t)n0 * Nn;
    const float* Brow = g_Vt + (size_t)vtrow * Nn;
    int NT = NC / 32;                 // n-tiles of 8 per warp (4/2/1)
    int biters = NC / 32;             // B cp.async float4 iters per thread

    int g = lane >> 2, t = lane & 3;
    int wm = (wid >> 2) * 64, wn = (wid & 3) * (NC / 4);
    float c[4][4][4] = {};

    const int NCH = Nn / 32;
    {
        float (*As)[36] = (float(*)[36])(dsm);
        float (*Bs)[36] = (float(*)[36])(dsm + NN_ASZ);
#pragma unroll
        for (int i = 0; i < 4; i++) {
            int idx = tid + i * 256, r = idx >> 3, k4 = (idx & 7) * 4;
            __pipeline_memcpy_async(&As[r][k4], &Arow[(size_t)r * Nn + k4], 16);
        }
#pragma unroll
        for (int i = 0; i < 4; i++) {
            if (i < biters) {
                int idx = tid + i * 256, r = idx >> 3, k4 = (idx & 7) * 4;
                __pipeline_memcpy_async(&Bs[r][k4], &Brow[(size_t)r * Nn + k4], 16);
            }
        }
        __pipeline_commit();
    }
#pragma unroll 1
    for (int ch = 0; ch < NCH; ch++) {
        __pipeline_wait_prior(0);
        __syncthreads();
        if (ch + 1 < NCH) {
            int s = (ch + 1) & 1, kk = (ch + 1) * 32;
            float (*As)[36] = (float(*)[36])(dsm + s * NN_STG);
            float (*Bs)[36] = (float(*)[36])(dsm + s * NN_STG + NN_ASZ);
#pragma unroll
            for (int i = 0; i < 4; i++) {
                int idx = tid + i * 256, r = idx >> 3, k4 = (idx & 7) * 4;
                __pipeline_memcpy_async(&As[r][k4], &Arow[(size_t)r * Nn + kk + k4], 16);
            }
#pragma unroll
            for (int i = 0; i < 4; i++) {
                if (i < biters) {
                    int idx = tid + i * 256, r = idx >> 3, k4 = (idx & 7) * 4;
                    __pipeline_memcpy_async(&Bs[r][k4], &Brow[(size_t)r * Nn + kk + k4], 16);
                }
            }
            __pipeline_commit();
        }
        float (*As)[36] = (float(*)[36])(dsm + (ch & 1) * NN_STG);
        float (*Bs)[36] = (float(*)[36])(dsm + (ch & 1) * NN_STG + NN_ASZ);
#pragma unroll
        for (int k8 = 0; k8 < 32; k8 += 8) {
            uint32_t a[4][4];
#pragma unroll
            for (int mt = 0; mt < 4; mt++) {
                int r = wm + mt * 16 + g;
                a[mt][0] = __float_as_uint(As[r][k8 + t]);
                a[mt][1] = __float_as_uint(As[r + 8][k8 + t]);
                a[mt][2] = __float_as_uint(As[r][k8 + t + 4]);
                a[mt][3] = __float_as_uint(As[r + 8][k8 + t + 4]);
            }
#pragma unroll
            for (int nt = 0; nt < 4; nt++) {
                if (nt < NT) {
                    int rn = wn + nt * 8 + g;
                    uint32_t b[2] = {__float_as_uint(Bs[rn][k8 + t]), __float_as_uint(Bs[rn][k8 + t + 4])};
#pragma unroll
                    for (int mt = 0; mt < 4; mt++) mma8(c[mt][nt], a[mt], b);
                }
            }
        }
    }
#pragma unroll
    for (int mt = 0; mt < 4; mt++)
#pragma unroll
        for (int nt = 0; nt < 4; nt++) {
            if (nt < NT) {
                int row = n0 + wm + mt * 16 + g, col = col0 + wn + nt * 8 + 2 * t;
                size_t i0 = (size_t)row * ldc + col, i1 = (size_t)(row + 8) * ldc + col;
                if (acc) {
                    float2 o0 = *(float2*)&Cp[i0], o1 = *(float2*)&Cp[i1];
                    *(float2*)&Cp[i0] = make_float2(o0.x + c[mt][nt][0], o0.y + c[mt][nt][1]);
                    *(float2*)&Cp[i1] = make_float2(o1.x + c[mt][nt][2], o1.y + c[mt][nt][3]);
                } else {
                    *(float2*)&Cp[i0] = make_float2(c[mt][nt][0], c[mt][nt][1]);
                    *(float2*)&Cp[i1] = make_float2(c[mt][nt][2], c[mt][nt][3]);
                }
            }
        }
}

// ---------------- softmax fused over heads + head-mean -> g_a ----------------
__global__ __launch_bounds__(256)
void softmax_kernel()
{
    int n = blockIdx.x;
    __shared__ float row[Nn];
    __shared__ float accr[Nn];
    __shared__ float red[256];
    int tid = threadIdx.x;
    for (int i = tid * 4; i < Nn; i += 1024) *(float4*)&accr[i] = make_float4(0.f, 0.f, 0.f, 0.f);

    for (int h = 0; h < 4; h++) {
        float* p = g_attn + ((size_t)h * Nn + n) * Nn;
        __syncthreads();
        float mx = -1e30f;
        for (int i = tid * 4; i < Nn; i += 1024) {
            float4 v = *(const float4*)&p[i];
            *(float4*)&row[i] = v;
            mx = fmaxf(mx, fmaxf(fmaxf(v.x, v.y), fmaxf(v.z, v.w)));
        }
        red[tid] = mx; __syncthreads();
        for (int s = 128; s > 0; s >>= 1) { if (tid < s) red[tid] = fmaxf(red[tid], red[tid + s]); __syncthreads(); }
        float m = red[0]; __syncthreads();
        float sum = 0.f;
        for (int i = tid; i < Nn; i += 256) { float e = __expf(row[i] - m); row[i] = e; sum += e; }
        red[tid] = sum; __syncthreads();
        for (int s = 128; s > 0; s >>= 1) { if (tid < s) red[tid] += red[tid + s]; __syncthreads(); }
        float inv = 1.f / red[0]; __syncthreads();
        for (int i = tid * 4; i < Nn; i += 1024) {
            float4 v = *(float4*)&row[i];
            float4 e = make_float4(v.x * inv, v.y * inv, v.z * inv, v.w * inv);
            *(float4*)&p[i] = make_float4(tf32f(e.x), tf32f(e.y), tf32f(e.z), tf32f(e.w));
            float4 a = *(float4*)&accr[i];
            *(float4*)&accr[i] = make_float4(a.x + e.x, a.y + e.y, a.z + e.z, a.w + e.w);
        }
    }
    __syncthreads();
    for (int i = tid * 4; i < Nn; i += 1024) {
        float4 a = *(float4*)&accr[i];
        *(float4*)&g_a[(size_t)n * Nn + i] =
            make_float4(tf32f(a.x * 0.25f), tf32f(a.y * 0.25f), tf32f(a.z * 0.25f), tf32f(a.w * 0.25f));
    }
}

// ---------------- build class weight matrices (reads g_a) ----------------
__global__ void build_w_kernel(const float* __restrict__ pos)
{
    for (size_t q = (size_t)blockIdx.x * blockDim.x + threadIdx.x; q < NNsz / 4;
         q += (size_t)gridDim.x * blockDim.x) {
        size_t i4 = q * 4;
        int n = (int)(i4 >> 11), m = (int)(i4 & 2047);
        float4 a4 = *(const float4*)&g_a[i4];
        float av[4] = {a4.x, a4.y, a4.z, a4.w};
        float pnx = pos[n * 3 + 0], pny = pos[n * 3 + 1], pnz = pos[n * 3 + 2];
        float o[8][4];
#pragma unroll
        for (int tt = 0; tt < 4; tt++) {
            float a = av[tt];
            float rx = pos[(m + tt) * 3 + 0] - pnx;
            float ry = pos[(m + tt) * 3 + 1] - pny;
            float rz = pos[(m + tt) * 3 + 2] - pnz;
            float r2 = rx * rx + ry * ry + rz * rz;
            bool ok = r2 > 1e-12f;
            float inv = ok ? rsqrtf(r2) : 0.f;
            float valid = ok ? 1.f : 0.f;
            float ux = rx * inv, uy = ry * inv, uz = rz * inv;
            o[0][tt] = tf32f(a * ux); o[1][tt] = tf32f(a * uy); o[2][tt] = tf32f(a * uz);
            o[3][tt] = tf32f(a * (SQRT3 * ux * uy));
            o[4][tt] = tf32f(a * (SQRT3 * uy * uz));
            o[5][tt] = tf32f(a * (0.5f * (3.f * uz * uz - 1.f)) * valid);
            o[6][tt] = tf32f(a * (SQRT3 * ux * uz));
            o[7][tt] = tf32f(a * (0.5f * SQRT3 * (ux * ux - uy * uy)));
        }
#pragma unroll
        for (int cc = 0; cc < 8; cc++)
            *(float4*)&g_W[cc * NNsz + i4] = make_float4(o[cc][0], o[cc][1], o[cc][2], o[cc][3]);
    }
}

// ---------------- invariants ----------------
__global__ void invariants_kernel()
{
    const int total = Nn * Ff;
    for (int i = blockIdx.x * blockDim.x + threadIdx.x; i < total; i += gridDim.x * blockDim.x) {
        int n = i / Ff, c = i % Ff;
        float v;
        if (c < D0) v = g_x0[n * D0 + c];
        else if (c < D0 + D1) {
            const float* p = &g_x1[(n * D1 + (c - D0)) * 3];
            v = sqrtf(p[0] * p[0] + p[1] * p[1] + p[2] * p[2]);
        } else {
            const float* p = &g_x2[(n * D2 + (c - D0 - D1)) * 5];
            v = sqrtf(p[0] * p[0] + p[1] * p[1] + p[2] * p[2] + p[3] * p[3] + p[4] * p[4]);
        }
        g_inv[i] = v;
    }
}

// ---------------- v1/v2 channel mixes (transposed tf32 writes) ----------------
__global__ __launch_bounds__(128)
void v1_kernel(const float* __restrict__ Wv1)
{
    int m = blockIdx.x;
    __shared__ float sx[D1 * 3];
    int tid = threadIdx.x;
    for (int i = tid; i < D1 * 3; i += 128) sx[i] = g_x1[m * D1 * 3 + i];
    __syncthreads();
    float a0 = 0.f, a1 = 0.f, a2 = 0.f;
#pragma unroll 8
    for (int d = 0; d < D1; d++) {
        float w = Wv1[d * D1 + tid];
        a0 += sx[d * 3 + 0] * w;
        a1 += sx[d * 3 + 1] * w;
        a2 += sx[d * 3 + 2] * w;
    }
    g_Vt[(size_t)(tid * 3 + 0) * Nn + m] = tf32f(a0);
    g_Vt[(size_t)(tid * 3 + 1) * Nn + m] = tf32f(a1);
    g_Vt[(size_t)(tid * 3 + 2) * Nn + m] = tf32f(a2);
}

__global__ __launch_bounds__(32)
void v2_kernel(const float* __restrict__ Wv2)
{
    int m = blockIdx.x;
    __shared__ float sx[D2 * 5];
    int tid = threadIdx.x;
    for (int i = tid; i < D2 * 5; i += 32) sx[i] = g_x2[m * D2 * 5 + i];
    __syncthreads();
    float a[5] = {};
#pragma unroll 8
    for (int d = 0; d < D2; d++) {
        float w = Wv2[d * D2 + tid];
#pragma unroll
        for (int c = 0; c < 5; c++) a[c] += sx[d * 5 + c] * w;
    }
#pragma unroll
    for (int c = 0; c < 5; c++) g_Vt[(size_t)(384 + tid * 5 + c) * Nn + m] = tf32f(a[c]);
}

// ---------------- finalize / gate / zero ----------------
__global__ void finalize_kernel()
{
    const int total = Nn * 544;
    for (int i = blockIdx.x * blockDim.x + threadIdx.x; i < total; i += gridDim.x * blockDim.x) {
        int n = i / 544, t = i % 544;
        if (t < 384) {
            int d = t / 3, c = t % 3;
            g_x1[n * 384 + t] += g_agg[(size_t)n * 1088 + t] + g_agg[(size_t)n * 1088 + 544 + c * 128 + d];
        } else {
            int tt = t - 384, e = tt / 5, c = tt % 5;
            g_x2[n * 160 + tt] += g_agg[(size_t)n * 1088 + 384 + tt] + g_agg[(size_t)n * 1088 + 928 + c * 32 + e];
        }
    }
}

__global__ void gate_kernel()
{
    const int total = Nn * 544;
    for (int i = blockIdx.x * blockDim.x + threadIdx.x; i < total; i += gridDim.x * blockDim.x) {
        int n = i / 544, t = i % 544;
        if (t < 384) g_x1[n * 384 + t] *= g_gate[n * 160 + t / 3];
        else { int tt = t - 384; g_x2[n * 160 + tt] *= g_gate[n * 160 + 128 + tt / 5]; }
    }
}

__global__ void zero_kernel()
{
    const int t1 = Nn * 384, total = Nn * 384 + Nn * 160;
    for (int i = blockIdx.x * blockDim.x + threadIdx.x; i < total; i += gridDim.x * blockDim.x) {
        if (i < t1) g_x1[i] = 0.f; else g_x2[i - t1] = 0.f;
    }
}

// ---------------- host ----------------
static inline void launch_gemm(const float* A, const float* B, float* C, const float* bias,
                               int M, int N, int K, int lda, int ldb, int ldc,
                               int act, int accum, int transC = 0)
{
    dim3 grid((N + 63) / 64, (M + 63) / 64);
    gemm_f32<<<grid, 256>>>(A, B, C, bias, M, N, K, lda, ldb, ldc, act, accum, transC);
}

extern "C" void kernel_launch(void* const* d_in, const int* in_sizes, int n_in,
                              void* d_out, int out_size)
{
    const float* x     = (const float*)d_in[0];
    const float* pos   = (const float*)d_in[1];
    const float* emb_W = (const float*)d_in[2];
    const float* emb_b = (const float*)d_in[3];
    const float* Wq    = (const float*)d_in[4];
    const float* Wk    = (const float*)d_in[5];
    const float* Wv0   = (const float*)d_in[6];
    const float* Wv1   = (const float*)d_in[7];
    const float* Wv2   = (const float*)d_in[8];
    const float* Ws1   = (const float*)d_in[9];
    const float* Ws2   = (const float*)d_in[10];
    const float* Wffa  = (const float*)d_in[11];
    const float* Wffb  = (const float*)d_in[12];
    const float* Wg    = (const float*)d_in[13];
    const float* out_W = (const float*)d_in[14];
    const float* out_b = (const float*)d_in[15];
    float* out = (float*)d_out;

    static int once = 0;
    if (!once) {
        cudaFuncSetAttribute(logits_mma_kernel, cudaFuncAttributeMaxDynamicSharedMemorySize, LOG_SMEM);
        cudaFuncSetAttribute(nn_mma_kernel, cudaFuncAttributeMaxDynamicSharedMemorySize, NN_SMEM);
        once = 1;
    }

    void* vp;
    cudaGetSymbolAddress(&vp, g_x0);     float* px0   = (float*)vp;
    cudaGetSymbolAddress(&vp, g_inv);    float* pinv  = (float*)vp;
    cudaGetSymbolAddress(&vp, g_qk);     float* pqk   = (float*)vp;
    cudaGetSymbolAddress(&vp, g_Vt);     float* pVt   = (float*)vp;
    cudaGetSymbolAddress(&vp, g_ff);     float* pff   = (float*)vp;
    cudaGetSymbolAddress(&vp, g_gate);   float* pgate = (float*)vp;
    cudaGetSymbolAddress(&vp, g_qkpack); float* pqkp  = (float*)vp;
    cudaGetSymbolAddress(&vp, g_vpack);  float* pvp   = (float*)vp;
    cudaGetSymbolAddress(&vp, g_gpack);  float* pgp   = (float*)vp;
    cudaGetSymbolAddress(&vp, g_opack);  float* pop   = (float*)vp;

    pack_kernel<<<2048, 256>>>(Wq, Wk, Wv0, Ws1, Ws2, Wg, out_W);
    zero_kernel<<<512, 256>>>();
    launch_gemm(x, emb_W, px0, emb_b, Nn, D0, 118, 118, D0, D0, 0, 0);

    for (int l = 0; l < NL; l++) {
        const float* qk_l   = pqkp + (size_t)l * 416 * 512;
        const float* vp_l   = pvp  + (size_t)l * 256 * 448;
        const float* gp_l   = pgp  + (size_t)l * 416 * 192;
        const float* Wv1_l  = Wv1  + (size_t)l * D1 * D1;
        const float* Wv2_l  = Wv2  + (size_t)l * D2 * D2;
        const float* Wffa_l = Wffa + (size_t)l * D0 * 512;
        const float* Wffb_l = Wffb + (size_t)l * 512 * D0;

        invariants_kernel<<<1024, 256>>>();
        launch_gemm(pinv, qk_l, pqk, nullptr, Nn, 512, Ff, Ff, 512, 512, 0, 0);
        launch_gemm(px0, vp_l, pVt + (size_t)544 * Nn, nullptr, Nn, 416, D0, D0, 448, Nn, 0, 0, 1);
        v1_kernel<<<Nn, 128>>>(Wv1_l);
        v2_kernel<<<Nn, 32>>>(Wv2_l);

        logits_mma_kernel<<<dim3(16, 16, 4), 256, LOG_SMEM>>>(pqk);
        softmax_kernel<<<Nn, 256>>>();
        build_w_kernel<<<4096, 256>>>(pos);

        nn_mma_kernel<<<dim3(17, 16), 256, NN_SMEM>>>();
        finalize_kernel<<<1024, 256>>>();

        launch_gemm(px0, Wffa_l, pff, nullptr, Nn, 512, D0, D0, 512, 512, 1, 0);
        launch_gemm(pff, Wffb_l, px0, nullptr, Nn, D0, 512, 512, D0, D0, 0, 1);

        invariants_kernel<<<1024, 256>>>();
        launch_gemm(pinv, gp_l, pgate, nullptr, Nn, 160, Ff, Ff, 192, 160, 2, 0);
        gate_kernel<<<1024, 256>>>();
    }
    launch_gemm(px0, pop, out, out_b, Nn, NCLS, D0, D0, 64, NCLS, 0, 0);
}